// round 11
// baseline (speedup 1.0000x reference)
#include <cuda_runtime.h>
#include <math.h>
#include <stdint.h>

#define D 768
#define H 12
#define HD 64
#define DFF 3072
#define QKV3 2304
#define MAXTOK 8192
#define S_MAX 1024

// ---------------- scratch (static device globals; no allocation) ----------------
__device__ float g_ln[MAXTOK * D];
__device__ float g_qkv[MAXTOK * QKV3];
__device__ float g_attn[MAXTOK * D];
__device__ float g_x2[MAXTOK * D];
__device__ float g_h[MAXTOK * D];
__device__ float g_m[MAXTOK * DFF];

// ---------------- helpers ----------------
__device__ __forceinline__ uint32_t f2tf(float f) {
    uint32_t r;
    asm("cvt.rna.tf32.f32 %0, %1;" : "=r"(r) : "f"(f));
    return r;
}

__device__ __forceinline__ void mma_tf32(
    float& c0, float& c1, float& c2, float& c3,
    uint32_t a0, uint32_t a1, uint32_t a2, uint32_t a3,
    uint32_t b0, uint32_t b1)
{
    asm volatile(
        "mma.sync.aligned.m16n8k8.row.col.f32.tf32.tf32.f32 "
        "{%0,%1,%2,%3}, {%4,%5,%6,%7}, {%8,%9}, {%0,%1,%2,%3};"
        : "+f"(c0), "+f"(c1), "+f"(c2), "+f"(c3)
        : "r"(a0), "r"(a1), "r"(a2), "r"(a3), "r"(b0), "r"(b1));
}

__device__ __forceinline__ void cpa16(uint32_t dst, const void* src) {
    asm volatile("cp.async.cg.shared.global [%0], [%1], 16;" :: "r"(dst), "l"(src));
}
#define CP_COMMIT asm volatile("cp.async.commit_group;")
#define CP_WAIT(n) asm volatile("cp.async.wait_group %0;" :: "n"(n))

// ---------------- tensor-core GEMM: block 128x64, warp 32x32, 3 CTAs/SM ----------------
// 4-stage cp.async pipeline (R6 skeleton). A smem [m][k] stride 20; B smem [k][n] stride 72
// (both =4,8 mod 32 -> conflict-free fragment reads).
#define APAD 20
#define BPADn 72
#define STAGES 4

template <int EPI>
__global__ __launch_bounds__(256, 3) void gemm_mma(
    const float* __restrict__ A, const float* __restrict__ Bm,
    const float* __restrict__ bias, const float* __restrict__ res,
    float* __restrict__ C, int M, int N, int K)
{
    __shared__ uint32_t As[STAGES][128 * APAD];
    __shared__ uint32_t Bs[STAGES][16 * BPADn];

    int tid  = threadIdx.x;
    int warp = tid >> 5, lane = tid & 31;
    int wm = (warp >> 1) * 32;
    int wn = (warp & 1) * 32;
    int g  = lane >> 2;
    int t4 = lane & 3;

    int bm = blockIdx.y * 128;
    int bn = blockIdx.x * 64;

    // A staging: thread -> row tid/2, 8 floats at (tid&1)*8  (2x cpa16)
    int aRow = tid >> 1;
    int aCol = (tid & 1) * 8;
    int gaRow = bm + aRow; if (gaRow >= M) gaRow = M - 1;
    const float* Ag = A + (size_t)gaRow * K + aCol;
    // B staging: thread -> k-row tid/16, 4 floats at (tid&15)*4  (1x cpa16)
    int bRow = tid >> 4;
    int bCol = (tid & 15) * 4;
    const float* Bg = Bm + (size_t)bRow * N + bn + bCol;

    uint32_t aDst = (uint32_t)__cvta_generic_to_shared(&As[0][aRow * APAD + aCol]);
    uint32_t bDst = (uint32_t)__cvta_generic_to_shared(&Bs[0][bRow * BPADn + bCol]);
    const uint32_t ABUF = 128 * APAD * 4;
    const uint32_t BBUF = 16 * BPADn * 4;

    float acc[2][4][4];
    #pragma unroll
    for (int mi = 0; mi < 2; mi++)
        #pragma unroll
        for (int ni = 0; ni < 4; ni++)
            #pragma unroll
            for (int r = 0; r < 4; r++) acc[mi][ni][r] = 0.f;

    int T = K >> 4;

    #pragma unroll
    for (int s = 0; s < STAGES - 1; s++) {
        if (s < T) {
            cpa16(aDst + s * ABUF,      Ag + s * 16);
            cpa16(aDst + s * ABUF + 16, Ag + s * 16 + 4);
            cpa16(bDst + s * BBUF,      Bg + (size_t)s * 16 * N);
        }
        CP_COMMIT;
    }

    for (int t = 0; t < T; t++) {
        CP_WAIT(STAGES - 2);
        __syncthreads();

        int pf = t + STAGES - 1;
        if (pf < T) {
            uint32_t bo = pf & (STAGES - 1);
            cpa16(aDst + bo * ABUF,      Ag + pf * 16);
            cpa16(aDst + bo * ABUF + 16, Ag + pf * 16 + 4);
            cpa16(bDst + bo * BBUF,      Bg + (size_t)pf * 16 * N);
        }
        CP_COMMIT;

        const uint32_t* Asb = As[t & (STAGES - 1)];
        const uint32_t* Bsb = Bs[t & (STAGES - 1)];

        #pragma unroll
        for (int kk = 0; kk < 16; kk += 8) {
            uint32_t af[2][4];
            #pragma unroll
            for (int mi = 0; mi < 2; mi++) {
                int r0 = wm + mi * 16 + g;
                af[mi][0] = Asb[r0 * APAD + kk + t4];
                af[mi][1] = Asb[(r0 + 8) * APAD + kk + t4];
                af[mi][2] = Asb[r0 * APAD + kk + 4 + t4];
                af[mi][3] = Asb[(r0 + 8) * APAD + kk + 4 + t4];
            }
            uint32_t bf[4][2];
            #pragma unroll
            for (int ni = 0; ni < 4; ni++) {
                int c0 = wn + ni * 8 + g;
                bf[ni][0] = Bsb[(kk + t4) * BPADn + c0];
                bf[ni][1] = Bsb[(kk + 4 + t4) * BPADn + c0];
            }
            #pragma unroll
            for (int mi = 0; mi < 2; mi++)
                #pragma unroll
                for (int ni = 0; ni < 4; ni++)
                    mma_tf32(acc[mi][ni][0], acc[mi][ni][1], acc[mi][ni][2], acc[mi][ni][3],
                             af[mi][0], af[mi][1], af[mi][2], af[mi][3],
                             bf[ni][0], bf[ni][1]);
        }
    }

    #pragma unroll
    for (int mi = 0; mi < 2; mi++) {
        #pragma unroll
        for (int half = 0; half < 2; half++) {
            int row = bm + wm + mi * 16 + half * 8 + g;
            if (row >= M) continue;
            #pragma unroll
            for (int ni = 0; ni < 4; ni++) {
                int col = bn + wn + ni * 8 + t4 * 2;
                float v0 = acc[mi][ni][half * 2 + 0] + bias[col];
                float v1 = acc[mi][ni][half * 2 + 1] + bias[col + 1];
                if (EPI == 1) {
                    v0 += res[(size_t)row * N + col];
                    v1 += res[(size_t)row * N + col + 1];
                }
                if (EPI == 2) {
                    v0 = 0.5f * v0 * (1.0f + erff(v0 * 0.70710678118654752f));
                    v1 = 0.5f * v1 * (1.0f + erff(v1 * 0.70710678118654752f));
                }
                float2 o; o.x = v0; o.y = v1;
                *(float2*)(C + (size_t)row * N + col) = o;
            }
        }
    }
}

// ---------------- LayerNorm: one block per token row ----------------
__global__ __launch_bounds__(256) void ln_kernel(
    const float* __restrict__ x, const float* __restrict__ g,
    const float* __restrict__ b, float* __restrict__ out)
{
    int row = blockIdx.x;
    const float* xr = x + (size_t)row * D;
    int t = threadIdx.x;

    float v0 = xr[t], v1 = xr[t + 256], v2 = xr[t + 512];
    float s = v0 + v1 + v2;
    float sq = v0 * v0 + v1 * v1 + v2 * v2;

    #pragma unroll
    for (int off = 16; off > 0; off >>= 1) {
        s  += __shfl_xor_sync(0xFFFFFFFFu, s, off);
        sq += __shfl_xor_sync(0xFFFFFFFFu, sq, off);
    }
    __shared__ float ss[8], ssq[8];
    int wid = t >> 5, lid = t & 31;
    if (lid == 0) { ss[wid] = s; ssq[wid] = sq; }
    __syncthreads();
    if (wid == 0) {
        float a = (lid < 8) ? ss[lid] : 0.f;
        float aq = (lid < 8) ? ssq[lid] : 0.f;
        #pragma unroll
        for (int off = 4; off > 0; off >>= 1) {
            a  += __shfl_xor_sync(0xFFFFFFFFu, a, off);
            aq += __shfl_xor_sync(0xFFFFFFFFu, aq, off);
        }
        if (lid == 0) { ss[0] = a; ssq[0] = aq; }
    }
    __syncthreads();
    float mean = ss[0] * (1.0f / D);
    float var = ssq[0] * (1.0f / D) - mean * mean;
    float rstd = rsqrtf(var + 1e-6f);

    float* orow = out + (size_t)row * D;
    orow[t]       = (v0 - mean) * rstd * g[t]       + b[t];
    orow[t + 256] = (v1 - mean) * rstd * g[t + 256] + b[t + 256];
    orow[t + 512] = (v2 - mean) * rstd * g[t + 512] + b[t + 512];
}

// ---------------- tensor-core flash attention: Q-tile 128, 8 warps (R10, unchanged) ----------------
#define KT 32
#define QS 68
#define PS 36
#define QT2 128

__global__ __launch_bounds__(256) void attn_mma(
    const float* __restrict__ qkv, const int* __restrict__ cu,
    float* __restrict__ out)
{
    __shared__ uint32_t Qs[QT2 * QS];
    __shared__ uint32_t Ks[2][KT * QS];
    __shared__ uint32_t Vs[2][KT * QS];
    __shared__ uint32_t Ps[8][16 * PS];

    int b = blockIdx.z, h = blockIdx.y, qt = blockIdx.x;
    int s0 = cu[b];
    int len = cu[b + 1] - s0;
    if (qt * QT2 >= len) return;

    int tid = threadIdx.x;
    int warp = tid >> 5, lane = tid & 31;
    int g = lane >> 2, t4 = lane & 3;

    int krow = tid >> 3;
    int kcol = (tid & 7) * 8;
    uint32_t kDst = (uint32_t)__cvta_generic_to_shared(&Ks[0][krow * QS + kcol]);
    uint32_t vDst = (uint32_t)__cvta_generic_to_shared(&Vs[0][krow * QS + kcol]);
    const uint32_t KBUF = KT * QS * 4;
    int ntile = (len + KT - 1) / KT;

    {
        int gk = krow; if (gk >= len) gk = len - 1;
        const float* base = qkv + (size_t)(s0 + gk) * QKV3 + h * HD + kcol;
        #pragma unroll
        for (int i = 0; i < 2; i++) {
            cpa16(kDst + i * 16, base + D + i * 4);
            cpa16(vDst + i * 16, base + 2 * D + i * 4);
        }
        CP_COMMIT;
    }

    {
        int qr = tid >> 1;
        int qc = (tid & 1) * 32;
        int gq = qt * QT2 + qr; if (gq >= len) gq = len - 1;
        const float* src = qkv + (size_t)(s0 + gq) * QKV3 + h * HD + qc;
        uint32_t* dst = &Qs[qr * QS + qc];
        #pragma unroll
        for (int i = 0; i < 8; i++) {
            float4 v = *(const float4*)(src + i * 4);
            dst[i * 4 + 0] = f2tf(v.x * 0.125f);
            dst[i * 4 + 1] = f2tf(v.y * 0.125f);
            dst[i * 4 + 2] = f2tf(v.z * 0.125f);
            dst[i * 4 + 3] = f2tf(v.w * 0.125f);
        }
    }
    __syncthreads();

    uint32_t qf[8][4];
    int wq = warp * 16;
    #pragma unroll
    for (int ks = 0; ks < 8; ks++) {
        qf[ks][0] = Qs[(wq + g) * QS + ks * 8 + t4];
        qf[ks][1] = Qs[(wq + g + 8) * QS + ks * 8 + t4];
        qf[ks][2] = Qs[(wq + g) * QS + ks * 8 + 4 + t4];
        qf[ks][3] = Qs[(wq + g + 8) * QS + ks * 8 + 4 + t4];
    }

    float oa[8][4];
    #pragma unroll
    for (int vn = 0; vn < 8; vn++)
        #pragma unroll
        for (int r = 0; r < 4; r++) oa[vn][r] = 0.f;
    float lp0 = 0.f, lp1 = 0.f;

    for (int kt = 0; kt < ntile; kt++) {
        if (kt + 1 < ntile) {
            uint32_t bo = (kt + 1) & 1;
            int gk = (kt + 1) * KT + krow; if (gk >= len) gk = len - 1;
            const float* base = qkv + (size_t)(s0 + gk) * QKV3 + h * HD + kcol;
            #pragma unroll
            for (int i = 0; i < 2; i++) {
                cpa16(kDst + bo * KBUF + i * 16, base + D + i * 4);
                cpa16(vDst + bo * KBUF + i * 16, base + 2 * D + i * 4);
            }
            CP_COMMIT;
            CP_WAIT(1);
        } else {
            CP_WAIT(0);
        }
        __syncthreads();

        const uint32_t* Kb = Ks[kt & 1];
        const uint32_t* Vb = Vs[kt & 1];

        float sa[4][4];
        #pragma unroll
        for (int kn = 0; kn < 4; kn++)
            #pragma unroll
            for (int r = 0; r < 4; r++) sa[kn][r] = 0.f;

        #pragma unroll
        for (int ks = 0; ks < 8; ks++) {
            #pragma unroll
            for (int kn = 0; kn < 4; kn++) {
                uint32_t b0 = Kb[(kn * 8 + g) * QS + ks * 8 + t4];
                uint32_t b1 = Kb[(kn * 8 + g) * QS + ks * 8 + 4 + t4];
                mma_tf32(sa[kn][0], sa[kn][1], sa[kn][2], sa[kn][3],
                         qf[ks][0], qf[ks][1], qf[ks][2], qf[ks][3], b0, b1);
            }
        }

        uint32_t* pw = Ps[warp];
        #pragma unroll
        for (int kn = 0; kn < 4; kn++) {
            int c0 = kt * KT + kn * 8 + 2 * t4;
            float p0 = (c0     < len) ? __expf(sa[kn][0]) : 0.f;
            float p1 = (c0 + 1 < len) ? __expf(sa[kn][1]) : 0.f;
            float p2 = (c0     < len) ? __expf(sa[kn][2]) : 0.f;
            float p3 = (c0 + 1 < len) ? __expf(sa[kn][3]) : 0.f;
            lp0 += p0 + p1;
            lp1 += p2 + p3;
            pw[g * PS + kn * 8 + 2 * t4]       = f2tf(p0);
            pw[g * PS + kn * 8 + 2 * t4 + 1]   = f2tf(p1);
            pw[(g + 8) * PS + kn * 8 + 2 * t4]     = f2tf(p2);
            pw[(g + 8) * PS + kn * 8 + 2 * t4 + 1] = f2tf(p3);
        }
        __syncwarp();

        #pragma unroll
        for (int ks = 0; ks < 4; ks++) {
            uint32_t a0 = pw[g * PS + ks * 8 + t4];
            uint32_t a1 = pw[(g + 8) * PS + ks * 8 + t4];
            uint32_t a2 = pw[g * PS + ks * 8 + 4 + t4];
            uint32_t a3 = pw[(g + 8) * PS + ks * 8 + 4 + t4];
            #pragma unroll
            for (int vn = 0; vn < 8; vn++) {
                uint32_t b0 = Vb[(ks * 8 + t4) * QS + vn * 8 + g];
                uint32_t b1 = Vb[(ks * 8 + 4 + t4) * QS + vn * 8 + g];
                mma_tf32(oa[vn][0], oa[vn][1], oa[vn][2], oa[vn][3],
                         a0, a1, a2, a3, b0, b1);
            }
        }
        __syncthreads();
    }

    lp0 += __shfl_xor_sync(0xFFFFFFFFu, lp0, 1);
    lp0 += __shfl_xor_sync(0xFFFFFFFFu, lp0, 2);
    lp1 += __shfl_xor_sync(0xFFFFFFFFu, lp1, 1);
    lp1 += __shfl_xor_sync(0xFFFFFFFFu, lp1, 2);
    float inv0 = 1.f / lp0, inv1 = 1.f / lp1;

    int q0 = qt * QT2 + wq + g;
    int q1 = q0 + 8;
    if (q0 < len) {
        float* op = out + (size_t)(s0 + q0) * D + h * HD;
        #pragma unroll
        for (int vn = 0; vn < 8; vn++) {
            float2 v; v.x = oa[vn][0] * inv0; v.y = oa[vn][1] * inv0;
            *(float2*)(op + vn * 8 + 2 * t4) = v;
        }
    }
    if (q1 < len) {
        float* op = out + (size_t)(s0 + q1) * D + h * HD;
        #pragma unroll
        for (int vn = 0; vn < 8; vn++) {
            float2 v; v.x = oa[vn][2] * inv1; v.y = oa[vn][3] * inv1;
            *(float2*)(op + vn * 8 + 2 * t4) = v;
        }
    }
}

// ---------------- launch ----------------
extern "C" void kernel_launch(void* const* d_in, const int* in_sizes, int n_in,
                              void* d_out, int out_size)
{
    const float* x     = (const float*)d_in[0];
    const int*   cu    = (const int*)  d_in[1];
    const float* g1    = (const float*)d_in[2];
    const float* beta1 = (const float*)d_in[3];
    const float* Wqkv  = (const float*)d_in[4];
    const float* bqkv  = (const float*)d_in[5];
    const float* Wo    = (const float*)d_in[6];
    const float* bo    = (const float*)d_in[7];
    const float* g2    = (const float*)d_in[8];
    const float* beta2 = (const float*)d_in[9];
    const float* W1    = (const float*)d_in[10];
    const float* bfc1  = (const float*)d_in[11];
    const float* W2    = (const float*)d_in[12];
    const float* bfc2  = (const float*)d_in[13];
    float* out = (float*)d_out;

    int total = in_sizes[0] / D;
    int B = in_sizes[1] - 1;

    float *p_ln, *p_qkv, *p_attn, *p_x2, *p_h, *p_m;
    cudaGetSymbolAddress((void**)&p_ln,   g_ln);
    cudaGetSymbolAddress((void**)&p_qkv,  g_qkv);
    cudaGetSymbolAddress((void**)&p_attn, g_attn);
    cudaGetSymbolAddress((void**)&p_x2,   g_x2);
    cudaGetSymbolAddress((void**)&p_h,    g_h);
    cudaGetSymbolAddress((void**)&p_m,    g_m);

    int mtiles = (total + 127) / 128;

    ln_kernel<<<total, 256>>>(x, g1, beta1, p_ln);
    gemm_mma<0><<<dim3(QKV3 / 64, mtiles), 256>>>(p_ln, Wqkv, bqkv, nullptr, p_qkv, total, QKV3, D);
    attn_mma<<<dim3(S_MAX / QT2, H, B), 256>>>(p_qkv, cu, p_attn);
    gemm_mma<1><<<dim3(D / 64, mtiles), 256>>>(p_attn, Wo, bo, x, p_x2, total, D, D);
    ln_kernel<<<total, 256>>>(p_x2, g2, beta2, p_h);
    gemm_mma<2><<<dim3(DFF / 64, mtiles), 256>>>(p_h, W1, bfc1, nullptr, p_m, total, DFF, D);
    gemm_mma<1><<<dim3(D / 64, mtiles), 256>>>(p_m, W2, bfc2, p_x2, out, total, D, DFF);
}

// round 12
// speedup vs baseline: 1.0019x; 1.0019x over previous
#include <cuda_runtime.h>
#include <math.h>
#include <stdint.h>

#define D 768
#define H 12
#define HD 64
#define DFF 3072
#define QKV3 2304
#define MAXTOK 8192
#define S_MAX 1024

// ---------------- scratch (static device globals; no allocation) ----------------
__device__ float g_ln[MAXTOK * D];
__device__ float g_qkv[MAXTOK * QKV3];
__device__ float g_attn[MAXTOK * D];
__device__ float g_x2[MAXTOK * D];
__device__ float g_h[MAXTOK * D];
__device__ float g_m[MAXTOK * DFF];

// ---------------- helpers ----------------
__device__ __forceinline__ uint32_t f2tf(float f) {
    uint32_t r;
    asm("cvt.rna.tf32.f32 %0, %1;" : "=r"(r) : "f"(f));
    return r;
}

__device__ __forceinline__ void mma_tf32(
    float& c0, float& c1, float& c2, float& c3,
    uint32_t a0, uint32_t a1, uint32_t a2, uint32_t a3,
    uint32_t b0, uint32_t b1)
{
    asm volatile(
        "mma.sync.aligned.m16n8k8.row.col.f32.tf32.tf32.f32 "
        "{%0,%1,%2,%3}, {%4,%5,%6,%7}, {%8,%9}, {%0,%1,%2,%3};"
        : "+f"(c0), "+f"(c1), "+f"(c2), "+f"(c3)
        : "r"(a0), "r"(a1), "r"(a2), "r"(a3), "r"(b0), "r"(b1));
}

__device__ __forceinline__ void cpa16(uint32_t dst, const void* src) {
    asm volatile("cp.async.cg.shared.global [%0], [%1], 16;" :: "r"(dst), "l"(src));
}
#define CP_COMMIT asm volatile("cp.async.commit_group;")
#define CP_WAIT(n) asm volatile("cp.async.wait_group %0;" :: "n"(n))

// ---------------- tensor-core GEMM: block 128x128, 4 warps, warp 64x64 ----------------
// 4-stage cp.async pipeline. Fragment smem bytes per MMA cut 1.5x vs 32x64 warp
// (A 2KB + B 2KB per kk feed 32 MMAs). A stride 20, B stride 136 (conflict-free).
#define APAD 20
#define BPAD 136
#define STAGES 4

template <int EPI>
__global__ __launch_bounds__(128, 2) void gemm_mma(
    const float* __restrict__ A, const float* __restrict__ Bm,
    const float* __restrict__ bias, const float* __restrict__ res,
    float* __restrict__ C, int M, int N, int K)
{
    __shared__ uint32_t As[STAGES][128 * APAD];
    __shared__ uint32_t Bs[STAGES][16 * BPAD];

    int tid  = threadIdx.x;
    int warp = tid >> 5, lane = tid & 31;
    int wm = (warp >> 1) * 64;
    int wn = (warp & 1) * 64;
    int g  = lane >> 2;
    int t4 = lane & 3;

    int bm = blockIdx.y * 128;
    int bn = blockIdx.x * 128;

    // A staging: thread -> row tid (0..127), 16 floats (4x cpa16)
    int aRow = tid;
    int gaRow = bm + aRow; if (gaRow >= M) gaRow = M - 1;
    const float* Ag = A + (size_t)gaRow * K;
    // B staging: thread -> k-row tid/8, 16 floats at (tid&7)*16 (4x cpa16)
    int bRow = tid >> 3;
    int bCol = (tid & 7) * 16;
    const float* Bg = Bm + (size_t)bRow * N + bn + bCol;

    uint32_t aDst = (uint32_t)__cvta_generic_to_shared(&As[0][aRow * APAD]);
    uint32_t bDst = (uint32_t)__cvta_generic_to_shared(&Bs[0][bRow * BPAD + bCol]);
    const uint32_t ABUF = 128 * APAD * 4;
    const uint32_t BBUF = 16 * BPAD * 4;

    float acc[4][8][4];
    #pragma unroll
    for (int mi = 0; mi < 4; mi++)
        #pragma unroll
        for (int ni = 0; ni < 8; ni++)
            #pragma unroll
            for (int r = 0; r < 4; r++) acc[mi][ni][r] = 0.f;

    int T = K >> 4;

    #pragma unroll
    for (int s = 0; s < STAGES - 1; s++) {
        if (s < T) {
            #pragma unroll
            for (int i = 0; i < 4; i++) {
                cpa16(aDst + s * ABUF + i * 16, Ag + s * 16 + i * 4);
                cpa16(bDst + s * BBUF + i * 16, Bg + (size_t)s * 16 * N + i * 4);
            }
        }
        CP_COMMIT;
    }

    for (int t = 0; t < T; t++) {
        CP_WAIT(STAGES - 2);
        __syncthreads();

        int pf = t + STAGES - 1;
        if (pf < T) {
            uint32_t bo = pf & (STAGES - 1);
            #pragma unroll
            for (int i = 0; i < 4; i++) {
                cpa16(aDst + bo * ABUF + i * 16, Ag + pf * 16 + i * 4);
                cpa16(bDst + bo * BBUF + i * 16, Bg + (size_t)pf * 16 * N + i * 4);
            }
        }
        CP_COMMIT;

        const uint32_t* Asb = As[t & (STAGES - 1)];
        const uint32_t* Bsb = Bs[t & (STAGES - 1)];

        #pragma unroll
        for (int kk = 0; kk < 16; kk += 8) {
            uint32_t af[4][4];
            #pragma unroll
            for (int mi = 0; mi < 4; mi++) {
                int r0 = wm + mi * 16 + g;
                af[mi][0] = Asb[r0 * APAD + kk + t4];
                af[mi][1] = Asb[(r0 + 8) * APAD + kk + t4];
                af[mi][2] = Asb[r0 * APAD + kk + 4 + t4];
                af[mi][3] = Asb[(r0 + 8) * APAD + kk + 4 + t4];
            }
            uint32_t bf[8][2];
            #pragma unroll
            for (int ni = 0; ni < 8; ni++) {
                int c0 = wn + ni * 8 + g;
                bf[ni][0] = Bsb[(kk + t4) * BPAD + c0];
                bf[ni][1] = Bsb[(kk + 4 + t4) * BPAD + c0];
            }
            #pragma unroll
            for (int mi = 0; mi < 4; mi++)
                #pragma unroll
                for (int ni = 0; ni < 8; ni++)
                    mma_tf32(acc[mi][ni][0], acc[mi][ni][1], acc[mi][ni][2], acc[mi][ni][3],
                             af[mi][0], af[mi][1], af[mi][2], af[mi][3],
                             bf[ni][0], bf[ni][1]);
        }
    }

    #pragma unroll
    for (int mi = 0; mi < 4; mi++) {
        #pragma unroll
        for (int half = 0; half < 2; half++) {
            int row = bm + wm + mi * 16 + half * 8 + g;
            if (row >= M) continue;
            #pragma unroll
            for (int ni = 0; ni < 8; ni++) {
                int col = bn + wn + ni * 8 + t4 * 2;
                float v0 = acc[mi][ni][half * 2 + 0] + bias[col];
                float v1 = acc[mi][ni][half * 2 + 1] + bias[col + 1];
                if (EPI == 1) {
                    v0 += res[(size_t)row * N + col];
                    v1 += res[(size_t)row * N + col + 1];
                }
                if (EPI == 2) {
                    v0 = 0.5f * v0 * (1.0f + erff(v0 * 0.70710678118654752f));
                    v1 = 0.5f * v1 * (1.0f + erff(v1 * 0.70710678118654752f));
                }
                float2 o; o.x = v0; o.y = v1;
                *(float2*)(C + (size_t)row * N + col) = o;
            }
        }
    }
}

// ---------------- LayerNorm: one block per token row ----------------
__global__ __launch_bounds__(256) void ln_kernel(
    const float* __restrict__ x, const float* __restrict__ g,
    const float* __restrict__ b, float* __restrict__ out)
{
    int row = blockIdx.x;
    const float* xr = x + (size_t)row * D;
    int t = threadIdx.x;

    float v0 = xr[t], v1 = xr[t + 256], v2 = xr[t + 512];
    float s = v0 + v1 + v2;
    float sq = v0 * v0 + v1 * v1 + v2 * v2;

    #pragma unroll
    for (int off = 16; off > 0; off >>= 1) {
        s  += __shfl_xor_sync(0xFFFFFFFFu, s, off);
        sq += __shfl_xor_sync(0xFFFFFFFFu, sq, off);
    }
    __shared__ float ss[8], ssq[8];
    int wid = t >> 5, lid = t & 31;
    if (lid == 0) { ss[wid] = s; ssq[wid] = sq; }
    __syncthreads();
    if (wid == 0) {
        float a = (lid < 8) ? ss[lid] : 0.f;
        float aq = (lid < 8) ? ssq[lid] : 0.f;
        #pragma unroll
        for (int off = 4; off > 0; off >>= 1) {
            a  += __shfl_xor_sync(0xFFFFFFFFu, a, off);
            aq += __shfl_xor_sync(0xFFFFFFFFu, aq, off);
        }
        if (lid == 0) { ss[0] = a; ssq[0] = aq; }
    }
    __syncthreads();
    float mean = ss[0] * (1.0f / D);
    float var = ssq[0] * (1.0f / D) - mean * mean;
    float rstd = rsqrtf(var + 1e-6f);

    float* orow = out + (size_t)row * D;
    orow[t]       = (v0 - mean) * rstd * g[t]       + b[t];
    orow[t + 256] = (v1 - mean) * rstd * g[t + 256] + b[t + 256];
    orow[t + 512] = (v2 - mean) * rstd * g[t + 512] + b[t + 512];
}

// ---------------- tensor-core flash attention: Q-tile 128, 8 warps (R10, unchanged) ----------------
#define KT 32
#define QS 68
#define PS 36
#define QT2 128

__global__ __launch_bounds__(256) void attn_mma(
    const float* __restrict__ qkv, const int* __restrict__ cu,
    float* __restrict__ out)
{
    __shared__ uint32_t Qs[QT2 * QS];
    __shared__ uint32_t Ks[2][KT * QS];
    __shared__ uint32_t Vs[2][KT * QS];
    __shared__ uint32_t Ps[8][16 * PS];

    int b = blockIdx.z, h = blockIdx.y, qt = blockIdx.x;
    int s0 = cu[b];
    int len = cu[b + 1] - s0;
    if (qt * QT2 >= len) return;

    int tid = threadIdx.x;
    int warp = tid >> 5, lane = tid & 31;
    int g = lane >> 2, t4 = lane & 3;

    int krow = tid >> 3;
    int kcol = (tid & 7) * 8;
    uint32_t kDst = (uint32_t)__cvta_generic_to_shared(&Ks[0][krow * QS + kcol]);
    uint32_t vDst = (uint32_t)__cvta_generic_to_shared(&Vs[0][krow * QS + kcol]);
    const uint32_t KBUF = KT * QS * 4;
    int ntile = (len + KT - 1) / KT;

    {
        int gk = krow; if (gk >= len) gk = len - 1;
        const float* base = qkv + (size_t)(s0 + gk) * QKV3 + h * HD + kcol;
        #pragma unroll
        for (int i = 0; i < 2; i++) {
            cpa16(kDst + i * 16, base + D + i * 4);
            cpa16(vDst + i * 16, base + 2 * D + i * 4);
        }
        CP_COMMIT;
    }

    {
        int qr = tid >> 1;
        int qc = (tid & 1) * 32;
        int gq = qt * QT2 + qr; if (gq >= len) gq = len - 1;
        const float* src = qkv + (size_t)(s0 + gq) * QKV3 + h * HD + qc;
        uint32_t* dst = &Qs[qr * QS + qc];
        #pragma unroll
        for (int i = 0; i < 8; i++) {
            float4 v = *(const float4*)(src + i * 4);
            dst[i * 4 + 0] = f2tf(v.x * 0.125f);
            dst[i * 4 + 1] = f2tf(v.y * 0.125f);
            dst[i * 4 + 2] = f2tf(v.z * 0.125f);
            dst[i * 4 + 3] = f2tf(v.w * 0.125f);
        }
    }
    __syncthreads();

    uint32_t qf[8][4];
    int wq = warp * 16;
    #pragma unroll
    for (int ks = 0; ks < 8; ks++) {
        qf[ks][0] = Qs[(wq + g) * QS + ks * 8 + t4];
        qf[ks][1] = Qs[(wq + g + 8) * QS + ks * 8 + t4];
        qf[ks][2] = Qs[(wq + g) * QS + ks * 8 + 4 + t4];
        qf[ks][3] = Qs[(wq + g + 8) * QS + ks * 8 + 4 + t4];
    }

    float oa[8][4];
    #pragma unroll
    for (int vn = 0; vn < 8; vn++)
        #pragma unroll
        for (int r = 0; r < 4; r++) oa[vn][r] = 0.f;
    float lp0 = 0.f, lp1 = 0.f;

    for (int kt = 0; kt < ntile; kt++) {
        if (kt + 1 < ntile) {
            uint32_t bo = (kt + 1) & 1;
            int gk = (kt + 1) * KT + krow; if (gk >= len) gk = len - 1;
            const float* base = qkv + (size_t)(s0 + gk) * QKV3 + h * HD + kcol;
            #pragma unroll
            for (int i = 0; i < 2; i++) {
                cpa16(kDst + bo * KBUF + i * 16, base + D + i * 4);
                cpa16(vDst + bo * KBUF + i * 16, base + 2 * D + i * 4);
            }
            CP_COMMIT;
            CP_WAIT(1);
        } else {
            CP_WAIT(0);
        }
        __syncthreads();

        const uint32_t* Kb = Ks[kt & 1];
        const uint32_t* Vb = Vs[kt & 1];

        float sa[4][4];
        #pragma unroll
        for (int kn = 0; kn < 4; kn++)
            #pragma unroll
            for (int r = 0; r < 4; r++) sa[kn][r] = 0.f;

        #pragma unroll
        for (int ks = 0; ks < 8; ks++) {
            #pragma unroll
            for (int kn = 0; kn < 4; kn++) {
                uint32_t b0 = Kb[(kn * 8 + g) * QS + ks * 8 + t4];
                uint32_t b1 = Kb[(kn * 8 + g) * QS + ks * 8 + 4 + t4];
                mma_tf32(sa[kn][0], sa[kn][1], sa[kn][2], sa[kn][3],
                         qf[ks][0], qf[ks][1], qf[ks][2], qf[ks][3], b0, b1);
            }
        }

        uint32_t* pw = Ps[warp];
        #pragma unroll
        for (int kn = 0; kn < 4; kn++) {
            int c0 = kt * KT + kn * 8 + 2 * t4;
            float p0 = (c0     < len) ? __expf(sa[kn][0]) : 0.f;
            float p1 = (c0 + 1 < len) ? __expf(sa[kn][1]) : 0.f;
            float p2 = (c0     < len) ? __expf(sa[kn][2]) : 0.f;
            float p3 = (c0 + 1 < len) ? __expf(sa[kn][3]) : 0.f;
            lp0 += p0 + p1;
            lp1 += p2 + p3;
            pw[g * PS + kn * 8 + 2 * t4]       = f2tf(p0);
            pw[g * PS + kn * 8 + 2 * t4 + 1]   = f2tf(p1);
            pw[(g + 8) * PS + kn * 8 + 2 * t4]     = f2tf(p2);
            pw[(g + 8) * PS + kn * 8 + 2 * t4 + 1] = f2tf(p3);
        }
        __syncwarp();

        #pragma unroll
        for (int ks = 0; ks < 4; ks++) {
            uint32_t a0 = pw[g * PS + ks * 8 + t4];
            uint32_t a1 = pw[(g + 8) * PS + ks * 8 + t4];
            uint32_t a2 = pw[g * PS + ks * 8 + 4 + t4];
            uint32_t a3 = pw[(g + 8) * PS + ks * 8 + 4 + t4];
            #pragma unroll
            for (int vn = 0; vn < 8; vn++) {
                uint32_t b0 = Vb[(ks * 8 + t4) * QS + vn * 8 + g];
                uint32_t b1 = Vb[(ks * 8 + 4 + t4) * QS + vn * 8 + g];
                mma_tf32(oa[vn][0], oa[vn][1], oa[vn][2], oa[vn][3],
                         a0, a1, a2, a3, b0, b1);
            }
        }
        __syncthreads();
    }

    lp0 += __shfl_xor_sync(0xFFFFFFFFu, lp0, 1);
    lp0 += __shfl_xor_sync(0xFFFFFFFFu, lp0, 2);
    lp1 += __shfl_xor_sync(0xFFFFFFFFu, lp1, 1);
    lp1 += __shfl_xor_sync(0xFFFFFFFFu, lp1, 2);
    float inv0 = 1.f / lp0, inv1 = 1.f / lp1;

    int q0 = qt * QT2 + wq + g;
    int q1 = q0 + 8;
    if (q0 < len) {
        float* op = out + (size_t)(s0 + q0) * D + h * HD;
        #pragma unroll
        for (int vn = 0; vn < 8; vn++) {
            float2 v; v.x = oa[vn][0] * inv0; v.y = oa[vn][1] * inv0;
            *(float2*)(op + vn * 8 + 2 * t4) = v;
        }
    }
    if (q1 < len) {
        float* op = out + (size_t)(s0 + q1) * D + h * HD;
        #pragma unroll
        for (int vn = 0; vn < 8; vn++) {
            float2 v; v.x = oa[vn][2] * inv1; v.y = oa[vn][3] * inv1;
            *(float2*)(op + vn * 8 + 2 * t4) = v;
        }
    }
}

// ---------------- launch ----------------
extern "C" void kernel_launch(void* const* d_in, const int* in_sizes, int n_in,
                              void* d_out, int out_size)
{
    const float* x     = (const float*)d_in[0];
    const int*   cu    = (const int*)  d_in[1];
    const float* g1    = (const float*)d_in[2];
    const float* beta1 = (const float*)d_in[3];
    const float* Wqkv  = (const float*)d_in[4];
    const float* bqkv  = (const float*)d_in[5];
    const float* Wo    = (const float*)d_in[6];
    const float* bo    = (const float*)d_in[7];
    const float* g2    = (const float*)d_in[8];
    const float* beta2 = (const float*)d_in[9];
    const float* W1    = (const float*)d_in[10];
    const float* bfc1  = (const float*)d_in[11];
    const float* W2    = (const float*)d_in[12];
    const float* bfc2  = (const float*)d_in[13];
    float* out = (float*)d_out;

    int total = in_sizes[0] / D;
    int B = in_sizes[1] - 1;

    float *p_ln, *p_qkv, *p_attn, *p_x2, *p_h, *p_m;
    cudaGetSymbolAddress((void**)&p_ln,   g_ln);
    cudaGetSymbolAddress((void**)&p_qkv,  g_qkv);
    cudaGetSymbolAddress((void**)&p_attn, g_attn);
    cudaGetSymbolAddress((void**)&p_x2,   g_x2);
    cudaGetSymbolAddress((void**)&p_h,    g_h);
    cudaGetSymbolAddress((void**)&p_m,    g_m);

    int mtiles = (total + 127) / 128;

    ln_kernel<<<total, 256>>>(x, g1, beta1, p_ln);
    gemm_mma<0><<<dim3(QKV3 / 128, mtiles), 128>>>(p_ln, Wqkv, bqkv, nullptr, p_qkv, total, QKV3, D);
    attn_mma<<<dim3(S_MAX / QT2, H, B), 256>>>(p_qkv, cu, p_attn);
    gemm_mma<1><<<dim3(D / 128, mtiles), 128>>>(p_attn, Wo, bo, x, p_x2, total, D, D);
    ln_kernel<<<total, 256>>>(p_x2, g2, beta2, p_h);
    gemm_mma<2><<<dim3(DFF / 128, mtiles), 128>>>(p_h, W1, bfc1, nullptr, p_m, total, DFF, D);
    gemm_mma<1><<<dim3(D / 128, mtiles), 128>>>(p_m, W2, bfc2, p_x2, out, total, D, DFF);
}

// round 13
// speedup vs baseline: 1.1196x; 1.1175x over previous
#include <cuda_runtime.h>
#include <math.h>
#include <stdint.h>

#define D 768
#define H 12
#define HD 64
#define DFF 3072
#define QKV3 2304
#define MAXTOK 8192
#define S_MAX 1024

// ---------------- scratch (static device globals; no allocation) ----------------
__device__ float g_ln[MAXTOK * D];
__device__ float g_qkv[MAXTOK * QKV3];
__device__ float g_attn[MAXTOK * D];
__device__ float g_x2[MAXTOK * D];
__device__ float g_h[MAXTOK * D];
__device__ float g_m[MAXTOK * DFF];

// ---------------- helpers ----------------
__device__ __forceinline__ uint32_t f2tf(float f) {
    uint32_t r;
    asm("cvt.rna.tf32.f32 %0, %1;" : "=r"(r) : "f"(f));
    return r;
}

__device__ __forceinline__ void mma_tf32(
    float& c0, float& c1, float& c2, float& c3,
    uint32_t a0, uint32_t a1, uint32_t a2, uint32_t a3,
    uint32_t b0, uint32_t b1)
{
    asm volatile(
        "mma.sync.aligned.m16n8k8.row.col.f32.tf32.tf32.f32 "
        "{%0,%1,%2,%3}, {%4,%5,%6,%7}, {%8,%9}, {%0,%1,%2,%3};"
        : "+f"(c0), "+f"(c1), "+f"(c2), "+f"(c3)
        : "r"(a0), "r"(a1), "r"(a2), "r"(a3), "r"(b0), "r"(b1));
}

__device__ __forceinline__ void cpa16(uint32_t dst, const void* src) {
    asm volatile("cp.async.cg.shared.global [%0], [%1], 16;" :: "r"(dst), "l"(src));
}
#define CP_COMMIT asm volatile("cp.async.commit_group;")
#define CP_WAIT(n) asm volatile("cp.async.wait_group %0;" :: "n"(n))

// ---------------- tensor-core GEMM: block 128x128, warp 32x64, 5-stage cp.async ----------------
#define APAD 20
#define BPAD 136
#define STAGES 5

template <int EPI>
__global__ __launch_bounds__(256, 2) void gemm_mma(
    const float* __restrict__ A, const float* __restrict__ Bm,
    const float* __restrict__ bias, const float* __restrict__ res,
    float* __restrict__ C, int M, int N, int K)
{
    __shared__ uint32_t As[STAGES][128 * APAD];
    __shared__ uint32_t Bs[STAGES][16 * BPAD];

    int tid  = threadIdx.x;
    int warp = tid >> 5, lane = tid & 31;
    int wm = (warp >> 1) * 32;
    int wn = (warp & 1) * 64;
    int g  = lane >> 2;
    int t4 = lane & 3;

    int bm = blockIdx.y * 128;
    int bn = blockIdx.x * 128;

    int aRow = tid >> 1;
    int aCol = (tid & 1) * 8;
    int gaRow = bm + aRow; if (gaRow >= M) gaRow = M - 1;
    const float* Ag = A + (size_t)gaRow * K + aCol;
    int bRow = tid >> 4;
    int bCol = (tid & 15) * 8;
    const float* Bg = Bm + (size_t)bRow * N + bn + bCol;

    uint32_t aDst = (uint32_t)__cvta_generic_to_shared(&As[0][aRow * APAD + aCol]);
    uint32_t bDst = (uint32_t)__cvta_generic_to_shared(&Bs[0][bRow * BPAD + bCol]);
    const uint32_t ABUF = 128 * APAD * 4;
    const uint32_t BBUF = 16 * BPAD * 4;

    float acc[2][8][4];
    #pragma unroll
    for (int mi = 0; mi < 2; mi++)
        #pragma unroll
        for (int ni = 0; ni < 8; ni++)
            #pragma unroll
            for (int r = 0; r < 4; r++) acc[mi][ni][r] = 0.f;

    int T = K >> 4;

    #pragma unroll
    for (int s = 0; s < STAGES - 1; s++) {
        if (s < T) {
            cpa16(aDst + s * ABUF,      Ag + s * 16);
            cpa16(aDst + s * ABUF + 16, Ag + s * 16 + 4);
            cpa16(bDst + s * BBUF,      Bg + (size_t)s * 16 * N);
            cpa16(bDst + s * BBUF + 16, Bg + (size_t)s * 16 * N + 4);
        }
        CP_COMMIT;
    }

    for (int t = 0; t < T; t++) {
        CP_WAIT(STAGES - 2);
        __syncthreads();

        int pf = t + STAGES - 1;
        if (pf < T) {
            uint32_t bo = (uint32_t)(pf % STAGES);
            cpa16(aDst + bo * ABUF,      Ag + pf * 16);
            cpa16(aDst + bo * ABUF + 16, Ag + pf * 16 + 4);
            cpa16(bDst + bo * BBUF,      Bg + (size_t)pf * 16 * N);
            cpa16(bDst + bo * BBUF + 16, Bg + (size_t)pf * 16 * N + 4);
        }
        CP_COMMIT;

        const uint32_t* Asb = As[t % STAGES];
        const uint32_t* Bsb = Bs[t % STAGES];

        #pragma unroll
        for (int kk = 0; kk < 16; kk += 8) {
            uint32_t af[2][4];
            #pragma unroll
            for (int mi = 0; mi < 2; mi++) {
                int r0 = wm + mi * 16 + g;
                af[mi][0] = Asb[r0 * APAD + kk + t4];
                af[mi][1] = Asb[(r0 + 8) * APAD + kk + t4];
                af[mi][2] = Asb[r0 * APAD + kk + 4 + t4];
                af[mi][3] = Asb[(r0 + 8) * APAD + kk + 4 + t4];
            }
            uint32_t bf[8][2];
            #pragma unroll
            for (int ni = 0; ni < 8; ni++) {
                int c0 = wn + ni * 8 + g;
                bf[ni][0] = Bsb[(kk + t4) * BPAD + c0];
                bf[ni][1] = Bsb[(kk + 4 + t4) * BPAD + c0];
            }
            #pragma unroll
            for (int mi = 0; mi < 2; mi++)
                #pragma unroll
                for (int ni = 0; ni < 8; ni++)
                    mma_tf32(acc[mi][ni][0], acc[mi][ni][1], acc[mi][ni][2], acc[mi][ni][3],
                             af[mi][0], af[mi][1], af[mi][2], af[mi][3],
                             bf[ni][0], bf[ni][1]);
        }
    }

    #pragma unroll
    for (int mi = 0; mi < 2; mi++) {
        #pragma unroll
        for (int half = 0; half < 2; half++) {
            int row = bm + wm + mi * 16 + half * 8 + g;
            if (row >= M) continue;
            #pragma unroll
            for (int ni = 0; ni < 8; ni++) {
                int col = bn + wn + ni * 8 + t4 * 2;
                float v0 = acc[mi][ni][half * 2 + 0] + bias[col];
                float v1 = acc[mi][ni][half * 2 + 1] + bias[col + 1];
                if (EPI == 1) {
                    v0 += res[(size_t)row * N + col];
                    v1 += res[(size_t)row * N + col + 1];
                }
                if (EPI == 2) {
                    v0 = 0.5f * v0 * (1.0f + erff(v0 * 0.70710678118654752f));
                    v1 = 0.5f * v1 * (1.0f + erff(v1 * 0.70710678118654752f));
                }
                float2 o; o.x = v0; o.y = v1;
                *(float2*)(C + (size_t)row * N + col) = o;
            }
        }
    }
}

// ---------------- LayerNorm: one WARP per row (8 rows/block, shuffle-only) ----------------
__global__ __launch_bounds__(256) void ln_kernel(
    const float* __restrict__ x, const float* __restrict__ g,
    const float* __restrict__ b, float* __restrict__ out, int total)
{
    int row = blockIdx.x * 8 + (threadIdx.x >> 5);
    if (row >= total) return;
    int lane = threadIdx.x & 31;

    const float* xr = x + (size_t)row * D;
    float v[24];
    float s = 0.f, sq = 0.f;
    #pragma unroll
    for (int i = 0; i < 24; i++) {
        v[i] = xr[lane + i * 32];
        s += v[i];
        sq = fmaf(v[i], v[i], sq);
    }
    #pragma unroll
    for (int off = 16; off > 0; off >>= 1) {
        s  += __shfl_xor_sync(0xFFFFFFFFu, s, off);
        sq += __shfl_xor_sync(0xFFFFFFFFu, sq, off);
    }
    float mean = s * (1.0f / D);
    float var = sq * (1.0f / D) - mean * mean;
    float rstd = rsqrtf(var + 1e-6f);

    float* orow = out + (size_t)row * D;
    #pragma unroll
    for (int i = 0; i < 24; i++) {
        int c = lane + i * 32;
        orow[c] = (v[i] - mean) * rstd * g[c] + b[c];
    }
}

// ---------------- tensor-core flash attention: Q-tile 128, 8 warps (R10, unchanged) ----------------
#define KT 32
#define QS 68
#define PS 36
#define QT2 128

__global__ __launch_bounds__(256) void attn_mma(
    const float* __restrict__ qkv, const int* __restrict__ cu,
    float* __restrict__ out)
{
    __shared__ uint32_t Qs[QT2 * QS];
    __shared__ uint32_t Ks[2][KT * QS];
    __shared__ uint32_t Vs[2][KT * QS];
    __shared__ uint32_t Ps[8][16 * PS];

    int b = blockIdx.z, h = blockIdx.y, qt = blockIdx.x;
    int s0 = cu[b];
    int len = cu[b + 1] - s0;
    if (qt * QT2 >= len) return;

    int tid = threadIdx.x;
    int warp = tid >> 5, lane = tid & 31;
    int g = lane >> 2, t4 = lane & 3;

    int krow = tid >> 3;
    int kcol = (tid & 7) * 8;
    uint32_t kDst = (uint32_t)__cvta_generic_to_shared(&Ks[0][krow * QS + kcol]);
    uint32_t vDst = (uint32_t)__cvta_generic_to_shared(&Vs[0][krow * QS + kcol]);
    const uint32_t KBUF = KT * QS * 4;
    int ntile = (len + KT - 1) / KT;

    {
        int gk = krow; if (gk >= len) gk = len - 1;
        const float* base = qkv + (size_t)(s0 + gk) * QKV3 + h * HD + kcol;
        #pragma unroll
        for (int i = 0; i < 2; i++) {
            cpa16(kDst + i * 16, base + D + i * 4);
            cpa16(vDst + i * 16, base + 2 * D + i * 4);
        }
        CP_COMMIT;
    }

    {
        int qr = tid >> 1;
        int qc = (tid & 1) * 32;
        int gq = qt * QT2 + qr; if (gq >= len) gq = len - 1;
        const float* src = qkv + (size_t)(s0 + gq) * QKV3 + h * HD + qc;
        uint32_t* dst = &Qs[qr * QS + qc];
        #pragma unroll
        for (int i = 0; i < 8; i++) {
            float4 v = *(const float4*)(src + i * 4);
            dst[i * 4 + 0] = f2tf(v.x * 0.125f);
            dst[i * 4 + 1] = f2tf(v.y * 0.125f);
            dst[i * 4 + 2] = f2tf(v.z * 0.125f);
            dst[i * 4 + 3] = f2tf(v.w * 0.125f);
        }
    }
    __syncthreads();

    uint32_t qf[8][4];
    int wq = warp * 16;
    #pragma unroll
    for (int ks = 0; ks < 8; ks++) {
        qf[ks][0] = Qs[(wq + g) * QS + ks * 8 + t4];
        qf[ks][1] = Qs[(wq + g + 8) * QS + ks * 8 + t4];
        qf[ks][2] = Qs[(wq + g) * QS + ks * 8 + 4 + t4];
        qf[ks][3] = Qs[(wq + g + 8) * QS + ks * 8 + 4 + t4];
    }

    float oa[8][4];
    #pragma unroll
    for (int vn = 0; vn < 8; vn++)
        #pragma unroll
        for (int r = 0; r < 4; r++) oa[vn][r] = 0.f;
    float lp0 = 0.f, lp1 = 0.f;

    for (int kt = 0; kt < ntile; kt++) {
        if (kt + 1 < ntile) {
            uint32_t bo = (kt + 1) & 1;
            int gk = (kt + 1) * KT + krow; if (gk >= len) gk = len - 1;
            const float* base = qkv + (size_t)(s0 + gk) * QKV3 + h * HD + kcol;
            #pragma unroll
            for (int i = 0; i < 2; i++) {
                cpa16(kDst + bo * KBUF + i * 16, base + D + i * 4);
                cpa16(vDst + bo * KBUF + i * 16, base + 2 * D + i * 4);
            }
            CP_COMMIT;
            CP_WAIT(1);
        } else {
            CP_WAIT(0);
        }
        __syncthreads();

        const uint32_t* Kb = Ks[kt & 1];
        const uint32_t* Vb = Vs[kt & 1];

        float sa[4][4];
        #pragma unroll
        for (int kn = 0; kn < 4; kn++)
            #pragma unroll
            for (int r = 0; r < 4; r++) sa[kn][r] = 0.f;

        #pragma unroll
        for (int ks = 0; ks < 8; ks++) {
            #pragma unroll
            for (int kn = 0; kn < 4; kn++) {
                uint32_t b0 = Kb[(kn * 8 + g) * QS + ks * 8 + t4];
                uint32_t b1 = Kb[(kn * 8 + g) * QS + ks * 8 + 4 + t4];
                mma_tf32(sa[kn][0], sa[kn][1], sa[kn][2], sa[kn][3],
                         qf[ks][0], qf[ks][1], qf[ks][2], qf[ks][3], b0, b1);
            }
        }

        uint32_t* pw = Ps[warp];
        #pragma unroll
        for (int kn = 0; kn < 4; kn++) {
            int c0 = kt * KT + kn * 8 + 2 * t4;
            float p0 = (c0     < len) ? __expf(sa[kn][0]) : 0.f;
            float p1 = (c0 + 1 < len) ? __expf(sa[kn][1]) : 0.f;
            float p2 = (c0     < len) ? __expf(sa[kn][2]) : 0.f;
            float p3 = (c0 + 1 < len) ? __expf(sa[kn][3]) : 0.f;
            lp0 += p0 + p1;
            lp1 += p2 + p3;
            pw[g * PS + kn * 8 + 2 * t4]       = f2tf(p0);
            pw[g * PS + kn * 8 + 2 * t4 + 1]   = f2tf(p1);
            pw[(g + 8) * PS + kn * 8 + 2 * t4]     = f2tf(p2);
            pw[(g + 8) * PS + kn * 8 + 2 * t4 + 1] = f2tf(p3);
        }
        __syncwarp();

        #pragma unroll
        for (int ks = 0; ks < 4; ks++) {
            uint32_t a0 = pw[g * PS + ks * 8 + t4];
            uint32_t a1 = pw[(g + 8) * PS + ks * 8 + t4];
            uint32_t a2 = pw[g * PS + ks * 8 + 4 + t4];
            uint32_t a3 = pw[(g + 8) * PS + ks * 8 + 4 + t4];
            #pragma unroll
            for (int vn = 0; vn < 8; vn++) {
                uint32_t b0 = Vb[(ks * 8 + t4) * QS + vn * 8 + g];
                uint32_t b1 = Vb[(ks * 8 + 4 + t4) * QS + vn * 8 + g];
                mma_tf32(oa[vn][0], oa[vn][1], oa[vn][2], oa[vn][3],
                         a0, a1, a2, a3, b0, b1);
            }
        }
        __syncthreads();
    }

    lp0 += __shfl_xor_sync(0xFFFFFFFFu, lp0, 1);
    lp0 += __shfl_xor_sync(0xFFFFFFFFu, lp0, 2);
    lp1 += __shfl_xor_sync(0xFFFFFFFFu, lp1, 1);
    lp1 += __shfl_xor_sync(0xFFFFFFFFu, lp1, 2);
    float inv0 = 1.f / lp0, inv1 = 1.f / lp1;

    int q0 = qt * QT2 + wq + g;
    int q1 = q0 + 8;
    if (q0 < len) {
        float* op = out + (size_t)(s0 + q0) * D + h * HD;
        #pragma unroll
        for (int vn = 0; vn < 8; vn++) {
            float2 v; v.x = oa[vn][0] * inv0; v.y = oa[vn][1] * inv0;
            *(float2*)(op + vn * 8 + 2 * t4) = v;
        }
    }
    if (q1 < len) {
        float* op = out + (size_t)(s0 + q1) * D + h * HD;
        #pragma unroll
        for (int vn = 0; vn < 8; vn++) {
            float2 v; v.x = oa[vn][2] * inv1; v.y = oa[vn][3] * inv1;
            *(float2*)(op + vn * 8 + 2 * t4) = v;
        }
    }
}

// ---------------- launch ----------------
extern "C" void kernel_launch(void* const* d_in, const int* in_sizes, int n_in,
                              void* d_out, int out_size)
{
    const float* x     = (const float*)d_in[0];
    const int*   cu    = (const int*)  d_in[1];
    const float* g1    = (const float*)d_in[2];
    const float* beta1 = (const float*)d_in[3];
    const float* Wqkv  = (const float*)d_in[4];
    const float* bqkv  = (const float*)d_in[5];
    const float* Wo    = (const float*)d_in[6];
    const float* bo    = (const float*)d_in[7];
    const float* g2    = (const float*)d_in[8];
    const float* beta2 = (const float*)d_in[9];
    const float* W1    = (const float*)d_in[10];
    const float* bfc1  = (const float*)d_in[11];
    const float* W2    = (const float*)d_in[12];
    const float* bfc2  = (const float*)d_in[13];
    float* out = (float*)d_out;

    int total = in_sizes[0] / D;
    int B = in_sizes[1] - 1;

    float *p_ln, *p_qkv, *p_attn, *p_x2, *p_h, *p_m;
    cudaGetSymbolAddress((void**)&p_ln,   g_ln);
    cudaGetSymbolAddress((void**)&p_qkv,  g_qkv);
    cudaGetSymbolAddress((void**)&p_attn, g_attn);
    cudaGetSymbolAddress((void**)&p_x2,   g_x2);
    cudaGetSymbolAddress((void**)&p_h,    g_h);
    cudaGetSymbolAddress((void**)&p_m,    g_m);

    int mtiles = (total + 127) / 128;
    int lnblocks = (total + 7) / 8;

    ln_kernel<<<lnblocks, 256>>>(x, g1, beta1, p_ln, total);
    gemm_mma<0><<<dim3(QKV3 / 128, mtiles), 256>>>(p_ln, Wqkv, bqkv, nullptr, p_qkv, total, QKV3, D);
    attn_mma<<<dim3(S_MAX / QT2, H, B), 256>>>(p_qkv, cu, p_attn);
    gemm_mma<1><<<dim3(D / 128, mtiles), 256>>>(p_attn, Wo, bo, x, p_x2, total, D, D);
    ln_kernel<<<lnblocks, 256>>>(p_x2, g2, beta2, p_h, total);
    gemm_mma<2><<<dim3(DFF / 128, mtiles), 256>>>(p_h, W1, bfc1, nullptr, p_m, total, DFF, D);
    gemm_mma<1><<<dim3(D / 128, mtiles), 256>>>(p_m, W2, bfc2, p_x2, out, total, D, DFF);
}

// round 14
// speedup vs baseline: 1.1502x; 1.0273x over previous
#include <cuda_runtime.h>
#include <math.h>
#include <stdint.h>

#define D 768
#define H 12
#define HD 64
#define DFF 3072
#define QKV3 2304
#define MAXTOK 8192
#define S_MAX 1024

// ---------------- scratch (static device globals; no allocation) ----------------
__device__ float g_ln[MAXTOK * D];
__device__ float g_qkv[MAXTOK * QKV3];
__device__ float g_attn[MAXTOK * D];
__device__ float g_x2[MAXTOK * D];
__device__ float g_h[MAXTOK * D];
__device__ float g_m[MAXTOK * DFF];

// ---------------- helpers ----------------
__device__ __forceinline__ uint32_t f2tf(float f) {
    uint32_t r;
    asm("cvt.rna.tf32.f32 %0, %1;" : "=r"(r) : "f"(f));
    return r;
}

__device__ __forceinline__ void mma_tf32(
    float& c0, float& c1, float& c2, float& c3,
    uint32_t a0, uint32_t a1, uint32_t a2, uint32_t a3,
    uint32_t b0, uint32_t b1)
{
    asm volatile(
        "mma.sync.aligned.m16n8k8.row.col.f32.tf32.tf32.f32 "
        "{%0,%1,%2,%3}, {%4,%5,%6,%7}, {%8,%9}, {%0,%1,%2,%3};"
        : "+f"(c0), "+f"(c1), "+f"(c2), "+f"(c3)
        : "r"(a0), "r"(a1), "r"(a2), "r"(a3), "r"(b0), "r"(b1));
}

__device__ __forceinline__ void cpa16(uint32_t dst, const void* src) {
    asm volatile("cp.async.cg.shared.global [%0], [%1], 16;" :: "r"(dst), "l"(src));
}
#define CP_COMMIT asm volatile("cp.async.commit_group;")
#define CP_WAIT(n) asm volatile("cp.async.wait_group %0;" :: "n"(n))

// ---------------- tensor-core GEMM: block 128x128, warp 32x64, 4-stage (R10 exact) ----------------
#define APAD 20
#define BPAD 136
#define STAGES 4

template <int EPI>
__global__ __launch_bounds__(256, 2) void gemm_mma(
    const float* __restrict__ A, const float* __restrict__ Bm,
    const float* __restrict__ bias, const float* __restrict__ res,
    float* __restrict__ C, int M, int N, int K)
{
    __shared__ uint32_t As[STAGES][128 * APAD];
    __shared__ uint32_t Bs[STAGES][16 * BPAD];

    int tid  = threadIdx.x;
    int warp = tid >> 5, lane = tid & 31;
    int wm = (warp >> 1) * 32;
    int wn = (warp & 1) * 64;
    int g  = lane >> 2;
    int t4 = lane & 3;

    int bm = blockIdx.y * 128;
    int bn = blockIdx.x * 128;

    int aRow = tid >> 1;
    int aCol = (tid & 1) * 8;
    int gaRow = bm + aRow; if (gaRow >= M) gaRow = M - 1;
    const float* Ag = A + (size_t)gaRow * K + aCol;
    int bRow = tid >> 4;
    int bCol = (tid & 15) * 8;
    const float* Bg = Bm + (size_t)bRow * N + bn + bCol;

    uint32_t aDst = (uint32_t)__cvta_generic_to_shared(&As[0][aRow * APAD + aCol]);
    uint32_t bDst = (uint32_t)__cvta_generic_to_shared(&Bs[0][bRow * BPAD + bCol]);
    const uint32_t ABUF = 128 * APAD * 4;
    const uint32_t BBUF = 16 * BPAD * 4;

    float acc[2][8][4];
    #pragma unroll
    for (int mi = 0; mi < 2; mi++)
        #pragma unroll
        for (int ni = 0; ni < 8; ni++)
            #pragma unroll
            for (int r = 0; r < 4; r++) acc[mi][ni][r] = 0.f;

    int T = K >> 4;

    #pragma unroll
    for (int s = 0; s < STAGES - 1; s++) {
        if (s < T) {
            cpa16(aDst + s * ABUF,      Ag + s * 16);
            cpa16(aDst + s * ABUF + 16, Ag + s * 16 + 4);
            cpa16(bDst + s * BBUF,      Bg + (size_t)s * 16 * N);
            cpa16(bDst + s * BBUF + 16, Bg + (size_t)s * 16 * N + 4);
        }
        CP_COMMIT;
    }

    for (int t = 0; t < T; t++) {
        CP_WAIT(STAGES - 2);
        __syncthreads();

        int pf = t + STAGES - 1;
        if (pf < T) {
            uint32_t bo = pf & (STAGES - 1);
            cpa16(aDst + bo * ABUF,      Ag + pf * 16);
            cpa16(aDst + bo * ABUF + 16, Ag + pf * 16 + 4);
            cpa16(bDst + bo * BBUF,      Bg + (size_t)pf * 16 * N);
            cpa16(bDst + bo * BBUF + 16, Bg + (size_t)pf * 16 * N + 4);
        }
        CP_COMMIT;

        const uint32_t* Asb = As[t & (STAGES - 1)];
        const uint32_t* Bsb = Bs[t & (STAGES - 1)];

        #pragma unroll
        for (int kk = 0; kk < 16; kk += 8) {
            uint32_t af[2][4];
            #pragma unroll
            for (int mi = 0; mi < 2; mi++) {
                int r0 = wm + mi * 16 + g;
                af[mi][0] = Asb[r0 * APAD + kk + t4];
                af[mi][1] = Asb[(r0 + 8) * APAD + kk + t4];
                af[mi][2] = Asb[r0 * APAD + kk + 4 + t4];
                af[mi][3] = Asb[(r0 + 8) * APAD + kk + 4 + t4];
            }
            uint32_t bf[8][2];
            #pragma unroll
            for (int ni = 0; ni < 8; ni++) {
                int c0 = wn + ni * 8 + g;
                bf[ni][0] = Bsb[(kk + t4) * BPAD + c0];
                bf[ni][1] = Bsb[(kk + 4 + t4) * BPAD + c0];
            }
            #pragma unroll
            for (int mi = 0; mi < 2; mi++)
                #pragma unroll
                for (int ni = 0; ni < 8; ni++)
                    mma_tf32(acc[mi][ni][0], acc[mi][ni][1], acc[mi][ni][2], acc[mi][ni][3],
                             af[mi][0], af[mi][1], af[mi][2], af[mi][3],
                             bf[ni][0], bf[ni][1]);
        }
    }

    #pragma unroll
    for (int mi = 0; mi < 2; mi++) {
        #pragma unroll
        for (int half = 0; half < 2; half++) {
            int row = bm + wm + mi * 16 + half * 8 + g;
            if (row >= M) continue;
            #pragma unroll
            for (int ni = 0; ni < 8; ni++) {
                int col = bn + wn + ni * 8 + t4 * 2;
                float v0 = acc[mi][ni][half * 2 + 0] + bias[col];
                float v1 = acc[mi][ni][half * 2 + 1] + bias[col + 1];
                if (EPI == 1) {
                    v0 += res[(size_t)row * N + col];
                    v1 += res[(size_t)row * N + col + 1];
                }
                if (EPI == 2) {
                    v0 = 0.5f * v0 * (1.0f + erff(v0 * 0.70710678118654752f));
                    v1 = 0.5f * v1 * (1.0f + erff(v1 * 0.70710678118654752f));
                }
                float2 o; o.x = v0; o.y = v1;
                *(float2*)(C + (size_t)row * N + col) = o;
            }
        }
    }
}

// ---------------- LayerNorm: one WARP per row (8 rows/block, shuffle-only) ----------------
__global__ __launch_bounds__(256) void ln_kernel(
    const float* __restrict__ x, const float* __restrict__ g,
    const float* __restrict__ b, float* __restrict__ out, int total)
{
    int row = blockIdx.x * 8 + (threadIdx.x >> 5);
    if (row >= total) return;
    int lane = threadIdx.x & 31;

    const float* xr = x + (size_t)row * D;
    float v[24];
    float s = 0.f, sq = 0.f;
    #pragma unroll
    for (int i = 0; i < 24; i++) {
        v[i] = xr[lane + i * 32];
        s += v[i];
        sq = fmaf(v[i], v[i], sq);
    }
    #pragma unroll
    for (int off = 16; off > 0; off >>= 1) {
        s  += __shfl_xor_sync(0xFFFFFFFFu, s, off);
        sq += __shfl_xor_sync(0xFFFFFFFFu, sq, off);
    }
    float mean = s * (1.0f / D);
    float var = sq * (1.0f / D) - mean * mean;
    float rstd = rsqrtf(var + 1e-6f);

    float* orow = out + (size_t)row * D;
    #pragma unroll
    for (int i = 0; i < 24; i++) {
        int c = lane + i * 32;
        orow[c] = (v[i] - mean) * rstd * g[c] + b[c];
    }
}

// ---------------- tensor-core flash attention: Q-tile 128, 3-stage K/V, single sync ----------------
#define KT 32
#define QS 68
#define PS 36
#define QT2 128
#define KSTG 3

__global__ __launch_bounds__(256) void attn_mma(
    const float* __restrict__ qkv, const int* __restrict__ cu,
    float* __restrict__ out)
{
    __shared__ uint32_t Qs[QT2 * QS];
    __shared__ uint32_t Ks[KSTG][KT * QS];
    __shared__ uint32_t Vs[KSTG][KT * QS];
    __shared__ uint32_t Ps[8][16 * PS];

    int b = blockIdx.z, h = blockIdx.y, qt = blockIdx.x;
    int s0 = cu[b];
    int len = cu[b + 1] - s0;
    if (qt * QT2 >= len) return;

    int tid = threadIdx.x;
    int warp = tid >> 5, lane = tid & 31;
    int g = lane >> 2, t4 = lane & 3;

    // K/V staging: thread -> k-row tid/8, 8 floats at (tid&7)*8 (2x cpa16 each)
    int krow = tid >> 3;
    int kcol = (tid & 7) * 8;
    uint32_t kDst = (uint32_t)__cvta_generic_to_shared(&Ks[0][krow * QS + kcol]);
    uint32_t vDst = (uint32_t)__cvta_generic_to_shared(&Vs[0][krow * QS + kcol]);
    const uint32_t KBUF = KT * QS * 4;
    int ntile = (len + KT - 1) / KT;

    // prologue: K/V tiles 0,1 -> bufs 0,1 (2 committed groups)
    #pragma unroll
    for (int s = 0; s < KSTG - 1; s++) {
        if (s < ntile) {
            int gk = s * KT + krow; if (gk >= len) gk = len - 1;
            const float* base = qkv + (size_t)(s0 + gk) * QKV3 + h * HD + kcol;
            #pragma unroll
            for (int i = 0; i < 2; i++) {
                cpa16(kDst + (uint32_t)(s * KBUF) + i * 16, base + D + i * 4);
                cpa16(vDst + (uint32_t)(s * KBUF) + i * 16, base + 2 * D + i * 4);
            }
        }
        CP_COMMIT;
    }

    // Q tile (128x64) to smem: scaled by 1/8, tf32
    {
        int qr = tid >> 1;
        int qc = (tid & 1) * 32;
        int gq = qt * QT2 + qr; if (gq >= len) gq = len - 1;
        const float* src = qkv + (size_t)(s0 + gq) * QKV3 + h * HD + qc;
        uint32_t* dst = &Qs[qr * QS + qc];
        #pragma unroll
        for (int i = 0; i < 8; i++) {
            float4 v = *(const float4*)(src + i * 4);
            dst[i * 4 + 0] = f2tf(v.x * 0.125f);
            dst[i * 4 + 1] = f2tf(v.y * 0.125f);
            dst[i * 4 + 2] = f2tf(v.z * 0.125f);
            dst[i * 4 + 3] = f2tf(v.w * 0.125f);
        }
    }
    __syncthreads();

    uint32_t qf[8][4];
    int wq = warp * 16;
    #pragma unroll
    for (int ks = 0; ks < 8; ks++) {
        qf[ks][0] = Qs[(wq + g) * QS + ks * 8 + t4];
        qf[ks][1] = Qs[(wq + g + 8) * QS + ks * 8 + t4];
        qf[ks][2] = Qs[(wq + g) * QS + ks * 8 + 4 + t4];
        qf[ks][3] = Qs[(wq + g + 8) * QS + ks * 8 + 4 + t4];
    }

    float oa[8][4];
    #pragma unroll
    for (int vn = 0; vn < 8; vn++)
        #pragma unroll
        for (int r = 0; r < 4; r++) oa[vn][r] = 0.f;
    float lp0 = 0.f, lp1 = 0.f;

    for (int kt = 0; kt < ntile; kt++) {
        CP_WAIT(1);            // tile kt landed
        __syncthreads();       // all warps done with compute of kt-1 (buffer (kt+2)%3 reuse safe)

        int pf = kt + KSTG - 1;
        if (pf < ntile) {
            uint32_t bo = (uint32_t)(pf % KSTG);
            int gk = pf * KT + krow; if (gk >= len) gk = len - 1;
            const float* base = qkv + (size_t)(s0 + gk) * QKV3 + h * HD + kcol;
            #pragma unroll
            for (int i = 0; i < 2; i++) {
                cpa16(kDst + bo * KBUF + i * 16, base + D + i * 4);
                cpa16(vDst + bo * KBUF + i * 16, base + 2 * D + i * 4);
            }
        }
        CP_COMMIT;

        const uint32_t* Kb = Ks[kt % KSTG];
        const uint32_t* Vb = Vs[kt % KSTG];

        // S = Q K^T
        float sa[4][4];
        #pragma unroll
        for (int kn = 0; kn < 4; kn++)
            #pragma unroll
            for (int r = 0; r < 4; r++) sa[kn][r] = 0.f;

        #pragma unroll
        for (int ks = 0; ks < 8; ks++) {
            #pragma unroll
            for (int kn = 0; kn < 4; kn++) {
                uint32_t b0 = Kb[(kn * 8 + g) * QS + ks * 8 + t4];
                uint32_t b1 = Kb[(kn * 8 + g) * QS + ks * 8 + 4 + t4];
                mma_tf32(sa[kn][0], sa[kn][1], sa[kn][2], sa[kn][3],
                         qf[ks][0], qf[ks][1], qf[ks][2], qf[ks][3], b0, b1);
            }
        }

        // P = exp(S), masked; row sums; to smem
        uint32_t* pw = Ps[warp];
        #pragma unroll
        for (int kn = 0; kn < 4; kn++) {
            int c0 = kt * KT + kn * 8 + 2 * t4;
            float p0 = (c0     < len) ? __expf(sa[kn][0]) : 0.f;
            float p1 = (c0 + 1 < len) ? __expf(sa[kn][1]) : 0.f;
            float p2 = (c0     < len) ? __expf(sa[kn][2]) : 0.f;
            float p3 = (c0 + 1 < len) ? __expf(sa[kn][3]) : 0.f;
            lp0 += p0 + p1;
            lp1 += p2 + p3;
            pw[g * PS + kn * 8 + 2 * t4]       = f2tf(p0);
            pw[g * PS + kn * 8 + 2 * t4 + 1]   = f2tf(p1);
            pw[(g + 8) * PS + kn * 8 + 2 * t4]     = f2tf(p2);
            pw[(g + 8) * PS + kn * 8 + 2 * t4 + 1] = f2tf(p3);
        }
        __syncwarp();

        // O += P V
        #pragma unroll
        for (int ks = 0; ks < 4; ks++) {
            uint32_t a0 = pw[g * PS + ks * 8 + t4];
            uint32_t a1 = pw[(g + 8) * PS + ks * 8 + t4];
            uint32_t a2 = pw[g * PS + ks * 8 + 4 + t4];
            uint32_t a3 = pw[(g + 8) * PS + ks * 8 + 4 + t4];
            #pragma unroll
            for (int vn = 0; vn < 8; vn++) {
                uint32_t b0 = Vb[(ks * 8 + t4) * QS + vn * 8 + g];
                uint32_t b1 = Vb[(ks * 8 + 4 + t4) * QS + vn * 8 + g];
                mma_tf32(oa[vn][0], oa[vn][1], oa[vn][2], oa[vn][3],
                         a0, a1, a2, a3, b0, b1);
            }
        }
    }

    lp0 += __shfl_xor_sync(0xFFFFFFFFu, lp0, 1);
    lp0 += __shfl_xor_sync(0xFFFFFFFFu, lp0, 2);
    lp1 += __shfl_xor_sync(0xFFFFFFFFu, lp1, 1);
    lp1 += __shfl_xor_sync(0xFFFFFFFFu, lp1, 2);
    float inv0 = 1.f / lp0, inv1 = 1.f / lp1;

    int q0 = qt * QT2 + wq + g;
    int q1 = q0 + 8;
    if (q0 < len) {
        float* op = out + (size_t)(s0 + q0) * D + h * HD;
        #pragma unroll
        for (int vn = 0; vn < 8; vn++) {
            float2 v; v.x = oa[vn][0] * inv0; v.y = oa[vn][1] * inv0;
            *(float2*)(op + vn * 8 + 2 * t4) = v;
        }
    }
    if (q1 < len) {
        float* op = out + (size_t)(s0 + q1) * D + h * HD;
        #pragma unroll
        for (int vn = 0; vn < 8; vn++) {
            float2 v; v.x = oa[vn][2] * inv1; v.y = oa[vn][3] * inv1;
            *(float2*)(op + vn * 8 + 2 * t4) = v;
        }
    }
}

// ---------------- launch ----------------
extern "C" void kernel_launch(void* const* d_in, const int* in_sizes, int n_in,
                              void* d_out, int out_size)
{
    const float* x     = (const float*)d_in[0];
    const int*   cu    = (const int*)  d_in[1];
    const float* g1    = (const float*)d_in[2];
    const float* beta1 = (const float*)d_in[3];
    const float* Wqkv  = (const float*)d_in[4];
    const float* bqkv  = (const float*)d_in[5];
    const float* Wo    = (const float*)d_in[6];
    const float* bo    = (const float*)d_in[7];
    const float* g2    = (const float*)d_in[8];
    const float* beta2 = (const float*)d_in[9];
    const float* W1    = (const float*)d_in[10];
    const float* bfc1  = (const float*)d_in[11];
    const float* W2    = (const float*)d_in[12];
    const float* bfc2  = (const float*)d_in[13];
    float* out = (float*)d_out;

    int total = in_sizes[0] / D;
    int B = in_sizes[1] - 1;

    float *p_ln, *p_qkv, *p_attn, *p_x2, *p_h, *p_m;
    cudaGetSymbolAddress((void**)&p_ln,   g_ln);
    cudaGetSymbolAddress((void**)&p_qkv,  g_qkv);
    cudaGetSymbolAddress((void**)&p_attn, g_attn);
    cudaGetSymbolAddress((void**)&p_x2,   g_x2);
    cudaGetSymbolAddress((void**)&p_h,    g_h);
    cudaGetSymbolAddress((void**)&p_m,    g_m);

    int mtiles = (total + 127) / 128;
    int lnblocks = (total + 7) / 8;

    ln_kernel<<<lnblocks, 256>>>(x, g1, beta1, p_ln, total);
    gemm_mma<0><<<dim3(QKV3 / 128, mtiles), 256>>>(p_ln, Wqkv, bqkv, nullptr, p_qkv, total, QKV3, D);
    attn_mma<<<dim3(S_MAX / QT2, H, B), 256>>>(p_qkv, cu, p_attn);
    gemm_mma<1><<<dim3(D / 128, mtiles), 256>>>(p_attn, Wo, bo, x, p_x2, total, D, D);
    ln_kernel<<<lnblocks, 256>>>(p_x2, g2, beta2, p_h, total);
    gemm_mma<2><<<dim3(DFF / 128, mtiles), 256>>>(p_h, W1, bfc1, nullptr, p_m, total, DFF, D);
    gemm_mma<1><<<dim3(D / 128, mtiles), 256>>>(p_m, W2, bfc2, p_x2, out, total, D, DFF);
}

// round 15
// speedup vs baseline: 1.9310x; 1.6789x over previous
#include <cuda_runtime.h>
#include <cuda_fp16.h>
#include <math.h>
#include <stdint.h>

#define D 768
#define H 12
#define HD 64
#define DFF 3072
#define QKV3 2304
#define MAXTOK 8192
#define S_MAX 1024

// ---------------- scratch (static device globals; no allocation) ----------------
__device__ __half g_ln[MAXTOK * D];
__device__ __half g_qkv[MAXTOK * QKV3];
__device__ __half g_vT[H * HD * MAXTOK];
__device__ __half g_attn[MAXTOK * D];
__device__ float  g_x2[MAXTOK * D];
__device__ __half g_h[MAXTOK * D];
__device__ __half g_m[MAXTOK * DFF];
// transposed half weights: Wt[N][K]
#define WT_QKV 0
#define WT_O   1769472
#define WT_1   2359296
#define WT_2   4718592
__device__ __half g_wT[7077888];

// ---------------- helpers ----------------
__device__ __forceinline__ uint32_t pack2(float a, float b) {
    __half2 h = __floats2half2_rn(a, b);   // a -> low half
    return *reinterpret_cast<uint32_t*>(&h);
}

__device__ __forceinline__ void mma_f16(
    float& c0, float& c1, float& c2, float& c3,
    uint32_t a0, uint32_t a1, uint32_t a2, uint32_t a3,
    uint32_t b0, uint32_t b1)
{
    asm volatile(
        "mma.sync.aligned.m16n8k16.row.col.f32.f16.f16.f32 "
        "{%0,%1,%2,%3}, {%4,%5,%6,%7}, {%8,%9}, {%0,%1,%2,%3};"
        : "+f"(c0), "+f"(c1), "+f"(c2), "+f"(c3)
        : "r"(a0), "r"(a1), "r"(a2), "r"(a3), "r"(b0), "r"(b1));
}

__device__ __forceinline__ void cpa16(uint32_t dst, const void* src) {
    asm volatile("cp.async.cg.shared.global [%0], [%1], 16;" :: "r"(dst), "l"(src));
}
#define CP_COMMIT asm volatile("cp.async.commit_group;")
#define CP_WAIT(n) asm volatile("cp.async.wait_group %0;" :: "n"(n))

// ---------------- weight prep: W[K,N] fp32 -> Wt[N,K] half ----------------
__global__ __launch_bounds__(256) void prep_w(
    const float* __restrict__ W, __half* __restrict__ Wt, int K, int N)
{
    __shared__ float t[32][33];
    int n0 = blockIdx.x * 32, k0 = blockIdx.y * 32;
    int tx = threadIdx.x & 31, ty = threadIdx.x >> 5;
    #pragma unroll
    for (int i = 0; i < 4; i++)
        t[ty + 8 * i][tx] = W[(size_t)(k0 + ty + 8 * i) * N + n0 + tx];
    __syncthreads();
    #pragma unroll
    for (int i = 0; i < 4; i++)
        Wt[(size_t)(n0 + ty + 8 * i) * K + k0 + tx] = __float2half_rn(t[tx][ty + 8 * i]);
}

// ---------------- V transpose: g_qkv V-part [token][c] -> g_vT[c][token] ----------------
__global__ __launch_bounds__(256) void prep_vT(
    const __half* __restrict__ qkv, __half* __restrict__ vT)
{
    __shared__ __half t[32][33];
    int c0 = blockIdx.x * 32, tok0 = blockIdx.y * 32;
    int tx = threadIdx.x & 31, ty = threadIdx.x >> 5;
    #pragma unroll
    for (int i = 0; i < 4; i++)
        t[ty + 8 * i][tx] = qkv[(size_t)(tok0 + ty + 8 * i) * QKV3 + 2 * D + c0 + tx];
    __syncthreads();
    #pragma unroll
    for (int i = 0; i < 4; i++)
        vT[(size_t)(c0 + ty + 8 * i) * MAXTOK + tok0 + tx] = t[tx][ty + 8 * i];
}

// ---------------- LayerNorm: one WARP per row, fp32 in -> half out ----------------
__global__ __launch_bounds__(256) void ln_kernel(
    const float* __restrict__ x, const float* __restrict__ g,
    const float* __restrict__ b, __half* __restrict__ out, int total)
{
    int row = blockIdx.x * 8 + (threadIdx.x >> 5);
    if (row >= total) return;
    int lane = threadIdx.x & 31;

    const float* xr = x + (size_t)row * D;
    float v[24];
    float s = 0.f, sq = 0.f;
    #pragma unroll
    for (int i = 0; i < 24; i++) {
        v[i] = xr[lane + i * 32];
        s += v[i];
        sq = fmaf(v[i], v[i], sq);
    }
    #pragma unroll
    for (int off = 16; off > 0; off >>= 1) {
        s  += __shfl_xor_sync(0xFFFFFFFFu, s, off);
        sq += __shfl_xor_sync(0xFFFFFFFFu, sq, off);
    }
    float mean = s * (1.0f / D);
    float var = sq * (1.0f / D) - mean * mean;
    float rstd = rsqrtf(var + 1e-6f);

    __half* orow = out + (size_t)row * D;
    #pragma unroll
    for (int i = 0; i < 24; i++) {
        int c = lane + i * 32;
        orow[c] = __float2half_rn((v[i] - mean) * rstd * g[c] + b[c]);
    }
}

// ---------------- fp16 tensor-core GEMM: C = A[M,K] * Wt[N,K]^T + bias (+res/gelu) ----------------
// Block 128x128, warp 32x64, KTILE=32 (2 fp16 k-steps), 4-stage cp.async.
// A smem [m][k] and B smem [n][k]: rows of 16 words (32 halves), stride 20 -> conflict-free frags.
// EPI: 0 = bias -> half C ; 1 = bias + residual -> float C ; 2 = bias + GELU -> half C
#define GPAD 20
#define STAGES 4

template <int EPI>
__global__ __launch_bounds__(256, 2) void gemm_h(
    const __half* __restrict__ A, const __half* __restrict__ Bt,
    const float* __restrict__ bias, const float* __restrict__ res,
    void* __restrict__ Cv, int M, int N, int K)
{
    __shared__ uint32_t As[STAGES][128 * GPAD];
    __shared__ uint32_t Bs[STAGES][128 * GPAD];

    int tid  = threadIdx.x;
    int warp = tid >> 5, lane = tid & 31;
    int wm = (warp >> 1) * 32;
    int wn = (warp & 1) * 64;
    int g  = lane >> 2;
    int t4 = lane & 3;

    int bm = blockIdx.y * 128;
    int bn = blockIdx.x * 128;

    // staging: thread -> row tid/2, 32B half-row (tid&1); 2 cpa16 for A, 2 for B
    int row = tid >> 1;
    int hoff = (tid & 1);                 // 0/1 -> halves offset *16
    int gaRow = bm + row; if (gaRow >= M) gaRow = M - 1;
    const __half* Ag = A + (size_t)gaRow * K + hoff * 16;
    int gbRow = bn + row;
    const __half* Bg = Bt + (size_t)gbRow * K + hoff * 16;

    uint32_t aDst = (uint32_t)__cvta_generic_to_shared(&As[0][row * GPAD + hoff * 8]);
    uint32_t bDst = (uint32_t)__cvta_generic_to_shared(&Bs[0][row * GPAD + hoff * 8]);
    const uint32_t BUF = 128 * GPAD * 4;

    float acc[2][8][4];
    #pragma unroll
    for (int mi = 0; mi < 2; mi++)
        #pragma unroll
        for (int ni = 0; ni < 8; ni++)
            #pragma unroll
            for (int r = 0; r < 4; r++) acc[mi][ni][r] = 0.f;

    int T = K >> 5;      // 32-k tiles

    #pragma unroll
    for (int s = 0; s < STAGES - 1; s++) {
        if (s < T) {
            cpa16(aDst + s * BUF,      Ag + s * 32);
            cpa16(aDst + s * BUF + 16, Ag + s * 32 + 8);
            cpa16(bDst + s * BUF,      Bg + s * 32);
            cpa16(bDst + s * BUF + 16, Bg + s * 32 + 8);
        }
        CP_COMMIT;
    }

    for (int t = 0; t < T; t++) {
        CP_WAIT(STAGES - 2);
        __syncthreads();

        int pf = t + STAGES - 1;
        if (pf < T) {
            uint32_t bo = pf & (STAGES - 1);
            cpa16(aDst + bo * BUF,      Ag + pf * 32);
            cpa16(aDst + bo * BUF + 16, Ag + pf * 32 + 8);
            cpa16(bDst + bo * BUF,      Bg + pf * 32);
            cpa16(bDst + bo * BUF + 16, Bg + pf * 32 + 8);
        }
        CP_COMMIT;

        const uint32_t* Asb = As[t & (STAGES - 1)];
        const uint32_t* Bsb = Bs[t & (STAGES - 1)];

        #pragma unroll
        for (int ks = 0; ks < 2; ks++) {
            uint32_t af[2][4];
            #pragma unroll
            for (int mi = 0; mi < 2; mi++) {
                int r0 = wm + mi * 16 + g;
                af[mi][0] = Asb[r0 * GPAD + ks * 8 + t4];
                af[mi][1] = Asb[(r0 + 8) * GPAD + ks * 8 + t4];
                af[mi][2] = Asb[r0 * GPAD + ks * 8 + 4 + t4];
                af[mi][3] = Asb[(r0 + 8) * GPAD + ks * 8 + 4 + t4];
            }
            uint32_t bf[8][2];
            #pragma unroll
            for (int ni = 0; ni < 8; ni++) {
                int c0 = wn + ni * 8 + g;
                bf[ni][0] = Bsb[c0 * GPAD + ks * 8 + t4];
                bf[ni][1] = Bsb[c0 * GPAD + ks * 8 + 4 + t4];
            }
            #pragma unroll
            for (int mi = 0; mi < 2; mi++)
                #pragma unroll
                for (int ni = 0; ni < 8; ni++)
                    mma_f16(acc[mi][ni][0], acc[mi][ni][1], acc[mi][ni][2], acc[mi][ni][3],
                            af[mi][0], af[mi][1], af[mi][2], af[mi][3],
                            bf[ni][0], bf[ni][1]);
        }
    }

    // ---- epilogue ----
    #pragma unroll
    for (int mi = 0; mi < 2; mi++) {
        #pragma unroll
        for (int half = 0; half < 2; half++) {
            int orow = bm + wm + mi * 16 + half * 8 + g;
            if (orow >= M) continue;
            #pragma unroll
            for (int ni = 0; ni < 8; ni++) {
                int col = bn + wn + ni * 8 + t4 * 2;
                float v0 = acc[mi][ni][half * 2 + 0] + bias[col];
                float v1 = acc[mi][ni][half * 2 + 1] + bias[col + 1];
                if (EPI == 1) {
                    v0 += res[(size_t)orow * N + col];
                    v1 += res[(size_t)orow * N + col + 1];
                }
                if (EPI == 2) {
                    v0 = 0.5f * v0 * (1.0f + erff(v0 * 0.70710678118654752f));
                    v1 = 0.5f * v1 * (1.0f + erff(v1 * 0.70710678118654752f));
                }
                if (EPI == 1) {
                    float2 o; o.x = v0; o.y = v1;
                    *(float2*)((float*)Cv + (size_t)orow * N + col) = o;
                } else {
                    *(uint32_t*)((__half*)Cv + (size_t)orow * N + col) = pack2(v0, v1);
                }
            }
        }
    }
}

// ---------------- fp16 flash attention: Q-tile 128, 3-stage K/V, P stays in registers ----------------
#define KT 32
#define QSW 36    // Q/K smem row stride (words)
#define VSW 20    // Vt smem row stride (words)
#define QT2 128
#define KSTG 3

__global__ __launch_bounds__(256) void attn_h(
    const __half* __restrict__ qkv, const __half* __restrict__ vT,
    const int* __restrict__ cu, __half* __restrict__ out)
{
    __shared__ uint32_t Qs[QT2 * QSW];
    __shared__ uint32_t Ks[KSTG][KT * QSW];
    __shared__ uint32_t Vs[KSTG][HD * VSW];

    int b = blockIdx.z, h = blockIdx.y, qt = blockIdx.x;
    int s0 = cu[b];
    int len = cu[b + 1] - s0;
    if (qt * QT2 >= len) return;

    int tid = threadIdx.x;
    int warp = tid >> 5, lane = tid & 31;
    int g = lane >> 2, t4 = lane & 3;

    // K staging: 32 rows x 128B; thread -> row tid/8, 16B chunk (tid&7)
    int krow = tid >> 3;
    int kchk = tid & 7;
    uint32_t kDst = (uint32_t)__cvta_generic_to_shared(&Ks[0][krow * QSW + kchk * 4]);
    // V staging: 64 d-rows x 64B; thread -> row tid/4, 16B chunk (tid&3)
    int vrow = tid >> 2;
    int vchk = tid & 3;
    uint32_t vDst = (uint32_t)__cvta_generic_to_shared(&Vs[0][vrow * VSW + vchk * 4]);
    const __half* vbase = vT + (size_t)(h * HD + vrow) * MAXTOK + s0;
    const uint32_t KBUF = KT * QSW * 4;
    const uint32_t VBUF = HD * VSW * 4;
    int ntile = (len + KT - 1) / KT;

    // prologue: tiles 0,1
    #pragma unroll
    for (int s = 0; s < KSTG - 1; s++) {
        if (s < ntile) {
            int gk = s * KT + krow; if (gk >= len) gk = len - 1;
            cpa16(kDst + (uint32_t)(s * KBUF),
                  qkv + (size_t)(s0 + gk) * QKV3 + D + h * HD + kchk * 8);
            int tk = s * KT + vchk * 8; if (tk >= len) tk = 0;
            cpa16(vDst + (uint32_t)(s * VBUF), vbase + tk);
        }
        CP_COMMIT;
    }

    // Q tile (128 x 64 halves) -> smem, scaled by 1/8
    {
        int qr = tid >> 1;
        int qh = (tid & 1);
        int gq = qt * QT2 + qr; if (gq >= len) gq = len - 1;
        const uint32_t* src = (const uint32_t*)(qkv + (size_t)(s0 + gq) * QKV3 + h * HD + qh * 32);
        uint32_t* dst = &Qs[qr * QSW + qh * 16];
        const __half2 sc = __float2half2_rn(0.125f);
        #pragma unroll
        for (int i = 0; i < 16; i++) {
            __half2 v = *(const __half2*)&src[i];
            v = __hmul2(v, sc);
            dst[i] = *(uint32_t*)&v;
        }
    }
    __syncthreads();

    // Q fragments: 4 k-steps x 4 regs, register-resident
    uint32_t qf[4][4];
    int wq = warp * 16;
    #pragma unroll
    for (int ks = 0; ks < 4; ks++) {
        qf[ks][0] = Qs[(wq + g) * QSW + ks * 8 + t4];
        qf[ks][1] = Qs[(wq + g + 8) * QSW + ks * 8 + t4];
        qf[ks][2] = Qs[(wq + g) * QSW + ks * 8 + 4 + t4];
        qf[ks][3] = Qs[(wq + g + 8) * QSW + ks * 8 + 4 + t4];
    }

    float oa[8][4];
    #pragma unroll
    for (int vn = 0; vn < 8; vn++)
        #pragma unroll
        for (int r = 0; r < 4; r++) oa[vn][r] = 0.f;
    float lp0 = 0.f, lp1 = 0.f;

    for (int kt = 0; kt < ntile; kt++) {
        CP_WAIT(1);
        __syncthreads();

        int pf = kt + KSTG - 1;
        if (pf < ntile) {
            uint32_t bo = (uint32_t)(pf % KSTG);
            int gk = pf * KT + krow; if (gk >= len) gk = len - 1;
            cpa16(kDst + bo * KBUF,
                  qkv + (size_t)(s0 + gk) * QKV3 + D + h * HD + kchk * 8);
            int tk = pf * KT + vchk * 8; if (tk >= len) tk = 0;
            cpa16(vDst + bo * VBUF, vbase + tk);
        }
        CP_COMMIT;

        const uint32_t* Kb = Ks[kt % KSTG];
        const uint32_t* Vb = Vs[kt % KSTG];

        // S = Q K^T : 4 k-steps (d=64), 4 key groups
        float sa[4][4];
        #pragma unroll
        for (int kn = 0; kn < 4; kn++)
            #pragma unroll
            for (int r = 0; r < 4; r++) sa[kn][r] = 0.f;

        #pragma unroll
        for (int ks = 0; ks < 4; ks++) {
            #pragma unroll
            for (int kn = 0; kn < 4; kn++) {
                uint32_t b0 = Kb[(kn * 8 + g) * QSW + ks * 8 + t4];
                uint32_t b1 = Kb[(kn * 8 + g) * QSW + ks * 8 + 4 + t4];
                mma_f16(sa[kn][0], sa[kn][1], sa[kn][2], sa[kn][3],
                        qf[ks][0], qf[ks][1], qf[ks][2], qf[ks][3], b0, b1);
            }
        }

        // P = exp(S) masked; pack directly into PV a-fragments (no smem!)
        uint32_t ph[4][2];
        #pragma unroll
        for (int kn = 0; kn < 4; kn++) {
            int c0 = kt * KT + kn * 8 + 2 * t4;
            float p0 = (c0     < len) ? __expf(sa[kn][0]) : 0.f;
            float p1 = (c0 + 1 < len) ? __expf(sa[kn][1]) : 0.f;
            float p2 = (c0     < len) ? __expf(sa[kn][2]) : 0.f;
            float p3 = (c0 + 1 < len) ? __expf(sa[kn][3]) : 0.f;
            lp0 += p0 + p1;
            lp1 += p2 + p3;
            ph[kn][0] = pack2(p0, p1);
            ph[kn][1] = pack2(p2, p3);
        }

        // O += P V : 2 k-steps (32 keys), 8 d-groups
        #pragma unroll
        for (int ks = 0; ks < 2; ks++) {
            uint32_t a0 = ph[2 * ks][0];
            uint32_t a1 = ph[2 * ks][1];
            uint32_t a2 = ph[2 * ks + 1][0];
            uint32_t a3 = ph[2 * ks + 1][1];
            #pragma unroll
            for (int vn = 0; vn < 8; vn++) {
                uint32_t b0 = Vb[(vn * 8 + g) * VSW + ks * 8 + t4];
                uint32_t b1 = Vb[(vn * 8 + g) * VSW + ks * 8 + 4 + t4];
                mma_f16(oa[vn][0], oa[vn][1], oa[vn][2], oa[vn][3],
                        a0, a1, a2, a3, b0, b1);
            }
        }
    }

    lp0 += __shfl_xor_sync(0xFFFFFFFFu, lp0, 1);
    lp0 += __shfl_xor_sync(0xFFFFFFFFu, lp0, 2);
    lp1 += __shfl_xor_sync(0xFFFFFFFFu, lp1, 1);
    lp1 += __shfl_xor_sync(0xFFFFFFFFu, lp1, 2);
    float inv0 = 1.f / lp0, inv1 = 1.f / lp1;

    int q0 = qt * QT2 + wq + g;
    int q1 = q0 + 8;
    if (q0 < len) {
        __half* op = out + (size_t)(s0 + q0) * D + h * HD;
        #pragma unroll
        for (int vn = 0; vn < 8; vn++)
            *(uint32_t*)(op + vn * 8 + 2 * t4) = pack2(oa[vn][0] * inv0, oa[vn][1] * inv0);
    }
    if (q1 < len) {
        __half* op = out + (size_t)(s0 + q1) * D + h * HD;
        #pragma unroll
        for (int vn = 0; vn < 8; vn++)
            *(uint32_t*)(op + vn * 8 + 2 * t4) = pack2(oa[vn][2] * inv1, oa[vn][3] * inv1);
    }
}

// ---------------- launch ----------------
extern "C" void kernel_launch(void* const* d_in, const int* in_sizes, int n_in,
                              void* d_out, int out_size)
{
    const float* x     = (const float*)d_in[0];
    const int*   cu    = (const int*)  d_in[1];
    const float* g1    = (const float*)d_in[2];
    const float* beta1 = (const float*)d_in[3];
    const float* Wqkv  = (const float*)d_in[4];
    const float* bqkv  = (const float*)d_in[5];
    const float* Wo    = (const float*)d_in[6];
    const float* bo    = (const float*)d_in[7];
    const float* g2    = (const float*)d_in[8];
    const float* beta2 = (const float*)d_in[9];
    const float* W1    = (const float*)d_in[10];
    const float* bfc1  = (const float*)d_in[11];
    const float* W2    = (const float*)d_in[12];
    const float* bfc2  = (const float*)d_in[13];
    float* out = (float*)d_out;

    int total = in_sizes[0] / D;
    int B = in_sizes[1] - 1;

    __half *p_ln, *p_qkv, *p_vT, *p_attn, *p_h, *p_m, *p_wT;
    float *p_x2;
    cudaGetSymbolAddress((void**)&p_ln,   g_ln);
    cudaGetSymbolAddress((void**)&p_qkv,  g_qkv);
    cudaGetSymbolAddress((void**)&p_vT,   g_vT);
    cudaGetSymbolAddress((void**)&p_attn, g_attn);
    cudaGetSymbolAddress((void**)&p_x2,   g_x2);
    cudaGetSymbolAddress((void**)&p_h,    g_h);
    cudaGetSymbolAddress((void**)&p_m,    g_m);
    cudaGetSymbolAddress((void**)&p_wT,   g_wT);

    int mtiles = (total + 127) / 128;
    int lnblocks = (total + 7) / 8;

    // 0. weight prep (transpose + fp16)
    prep_w<<<dim3(QKV3 / 32, D / 32), 256>>>(Wqkv, p_wT + WT_QKV, D, QKV3);
    prep_w<<<dim3(D / 32, D / 32), 256>>>(Wo, p_wT + WT_O, D, D);
    prep_w<<<dim3(DFF / 32, D / 32), 256>>>(W1, p_wT + WT_1, D, DFF);
    prep_w<<<dim3(D / 32, DFF / 32), 256>>>(W2, p_wT + WT_2, DFF, D);

    // 1. LN1 -> half
    ln_kernel<<<lnblocks, 256>>>(x, g1, beta1, p_ln, total);
    // 2. QKV GEMM (half out)
    gemm_h<0><<<dim3(QKV3 / 128, mtiles), 256>>>(p_ln, p_wT + WT_QKV, bqkv, nullptr, p_qkv, total, QKV3, D);
    // 2b. V transpose for attention
    prep_vT<<<dim3(D / 32, (total + 31) / 32), 256>>>(p_qkv, p_vT);
    // 3. ragged attention (half out)
    attn_h<<<dim3(S_MAX / QT2, H, B), 256>>>(p_qkv, p_vT, cu, p_attn);
    // 4. Wo GEMM + residual(x) -> x2 (float out)
    gemm_h<1><<<dim3(D / 128, mtiles), 256>>>(p_attn, p_wT + WT_O, bo, x, p_x2, total, D, D);
    // 5. LN2 -> half
    ln_kernel<<<lnblocks, 256>>>(p_x2, g2, beta2, p_h, total);
    // 6. FFN1 + GELU (half out)
    gemm_h<2><<<dim3(DFF / 128, mtiles), 256>>>(p_h, p_wT + WT_1, bfc1, nullptr, p_m, total, DFF, D);
    // 7. FFN2 + residual(x2) -> out (float)
    gemm_h<1><<<dim3(D / 128, mtiles), 256>>>(p_m, p_wT + WT_2, bfc2, p_x2, out, total, D, DFF);
}